// round 14
// baseline (speedup 1.0000x reference)
#include <cuda_runtime.h>
#include <cuda_bf16.h>
#include <cstdint>

#define Mdim 512
#define Cdim 256
#define Bdim 8
#define Tdim 32
#define BT 256            // B*T
#define MC 131072         // M*C
#define TOPKK 8
#define LAMf 0.05f
#define RHOf 0.9f
#define DLRf 0.03f
#define EPSF 1e-12f
#define LN_EPSF 1e-5f
#define AP 776            // padded A row pitch (floats)
#define NTILE 32          // C / 8 column tiles
#define CPT 8             // columns per tile
#define CPITCH 520        // smem cand pitch

// ---------------- scratch (device globals; no allocation allowed) ----------
__device__ float g_LNu[BT * Mdim];
__device__ float g_A[BT * AP];                     // [u(512) | c_t(256)] rows
__device__ float g_Lu[BT * Cdim];
__device__ float g_ct[BT * Cdim];
__device__ int   g_aidx[BT * TOPKK];
__device__ float g_aval[BT * TOPKK];
__device__ float g_cand[(size_t)BT * MC];          // 128 MiB cand scratch / partials
__device__ float g_D[2][Bdim * Cdim * Mdim];       // ping-pong dictionary [b][c][m]
__device__ float g_zpart[(size_t)BT * NTILE * Mdim];
__device__ unsigned g_bar[Bdim];                   // per-batch step barriers (k_steps)
__device__ uint4 g_Abf_hi4[BT * 768 * 2 / 16];     // A hi bf16 (16B-aligned)
__device__ uint4 g_Abf_lo4[BT * 768 * 2 / 16];     // A lo bf16

// ---------------- helpers --------------------------------------------------
__device__ __forceinline__ uint32_t smem_u32(const void* p) {
    uint32_t a;
    asm("{ .reg .u64 t; cvta.to.shared.u64 t, %1; cvt.u32.u64 %0, t; }" : "=r"(a) : "l"(p));
    return a;
}
__device__ __forceinline__ void ldsm_x4(uint32_t* r, uint32_t addr) {
    asm volatile("ldmatrix.sync.aligned.m8n8.x4.shared.b16 {%0,%1,%2,%3}, [%4];"
        : "=r"(r[0]), "=r"(r[1]), "=r"(r[2]), "=r"(r[3]) : "r"(addr));
}
__device__ __forceinline__ void mma_bf16(float* c, const uint32_t* a, uint32_t b0, uint32_t b1) {
    asm volatile("mma.sync.aligned.m16n8k16.row.col.f32.bf16.bf16.f32 "
        "{%0,%1,%2,%3}, {%4,%5,%6,%7}, {%8,%9}, {%0,%1,%2,%3};"
        : "+f"(c[0]), "+f"(c[1]), "+f"(c[2]), "+f"(c[3])
        : "r"(a[0]), "r"(a[1]), "r"(a[2]), "r"(a[3]), "r"(b0), "r"(b1));
}
__device__ __forceinline__ void cpasync16(uint32_t dst, const void* src) {
    asm volatile("cp.async.cg.shared.global [%0], [%1], 16;" :: "r"(dst), "l"(src));
}
__device__ __forceinline__ float blockReduceSum(float v, float* sh) {
    __syncthreads();
    #pragma unroll
    for (int o = 16; o; o >>= 1) v += __shfl_xor_sync(0xffffffffu, v, o);
    int w = threadIdx.x >> 5, l = threadIdx.x & 31;
    if (l == 0) sh[w] = v;
    __syncthreads();
    if (w == 0) {
        float x = (l < (int)(blockDim.x >> 5)) ? sh[l] : 0.f;
        #pragma unroll
        for (int o = 4; o; o >>= 1) x += __shfl_xor_sync(0xffffffffu, x, o);
        if (l == 0) sh[0] = x;
    }
    __syncthreads();
    return sh[0];
}
__device__ __forceinline__ void bf_split(float v, __nv_bfloat16* ph, __nv_bfloat16* pl) {
    __nv_bfloat16 h = __float2bfloat16_rn(v);
    *ph = h;
    *pl = __float2bfloat16_rn(v - __bfloat162float(h));
}

// ---------------- K1: LN(u), fill A u-part + bf16 u split ------------------
__global__ void k1_lnu(const float* __restrict__ u,
                       const float* __restrict__ g, const float* __restrict__ bb) {
    __shared__ float sh[8];
    int r = blockIdx.x, tid = threadIdx.x;
    const float* ur = u + (size_t)r * Mdim;
    float x0 = ur[tid], x1 = ur[tid + 256];
    float s = blockReduceSum(x0 + x1, sh);
    float mu = s * (1.f / Mdim);
    float d0 = x0 - mu, d1 = x1 - mu;
    float var = blockReduceSum(d0 * d0 + d1 * d1, sh) * (1.f / Mdim);
    float inv = rsqrtf(var + LN_EPSF);
    g_LNu[(size_t)r * Mdim + tid]       = d0 * inv * g[tid] + bb[tid];
    g_LNu[(size_t)r * Mdim + tid + 256] = d1 * inv * g[tid + 256] + bb[tid + 256];
    g_A[(size_t)r * AP + tid]       = x0;
    g_A[(size_t)r * AP + tid + 256] = x1;
    __nv_bfloat16* ph = (__nv_bfloat16*)g_Abf_hi4;
    __nv_bfloat16* pl = (__nv_bfloat16*)g_Abf_lo4;
    bf_split(x0, ph + r * 768 + tid,       pl + r * 768 + tid);
    bf_split(x1, ph + r * 768 + tid + 256, pl + r * 768 + tid + 256);
}

// ---------------- K2: Lu = LN(u) @ W_cu^T ---------------------------------
__global__ void k2_lu(const float* __restrict__ Wcu) {
    __shared__ float ln[Mdim];
    int r = blockIdx.x, c = threadIdx.x;
    ln[c]       = g_LNu[(size_t)r * Mdim + c];
    ln[c + 256] = g_LNu[(size_t)r * Mdim + c + 256];
    __syncthreads();
    const float4* wr = (const float4*)(Wcu + (size_t)c * Mdim);
    float a0 = 0.f, a1 = 0.f, a2 = 0.f, a3 = 0.f;
    #pragma unroll 4
    for (int i = 0; i < 128; i += 4) {
        float4 w0 = wr[i],   w1 = wr[i+1], w2 = wr[i+2], w3 = wr[i+3];
        a0 = fmaf(w0.x, ln[4*i+0], fmaf(w0.y, ln[4*i+1], fmaf(w0.z, ln[4*i+2], fmaf(w0.w, ln[4*i+3], a0))));
        a1 = fmaf(w1.x, ln[4*i+4], fmaf(w1.y, ln[4*i+5], fmaf(w1.z, ln[4*i+6], fmaf(w1.w, ln[4*i+7], a1))));
        a2 = fmaf(w2.x, ln[4*i+8], fmaf(w2.y, ln[4*i+9], fmaf(w2.z, ln[4*i+10], fmaf(w2.w, ln[4*i+11], a2))));
        a3 = fmaf(w3.x, ln[4*i+12], fmaf(w3.y, ln[4*i+13], fmaf(w3.z, ln[4*i+14], fmaf(w3.w, ln[4*i+15], a3))));
    }
    g_Lu[r * Cdim + c] = (a0 + a1) + (a2 + a3);
}

// ---------------- K3: recurrence, Wcc resident (smem+regs) + c bf16 split --
#define K3_PITCH 130
#define K3W_SMEM (Cdim * K3_PITCH * 4)      // 133120 bytes

__global__ void __launch_bounds__(256, 1)
k3_rec(const float* __restrict__ Wcc, const float* __restrict__ valid,
       const float* __restrict__ lncg, const float* __restrict__ lncb) {
    extern __shared__ float wsm[];          // [256][K3_PITCH]
    __shared__ float sh[16];
    __shared__ float lnc[Cdim];
    __shared__ float shr_sm[Cdim];
    __shared__ float cwv[64];
    __shared__ int   cwi[64];
    __shared__ float t8v[TOPKK];
    __shared__ int   t8i[TOPKK];
    int b = blockIdx.x, c = threadIdx.x;
    int w = c >> 5, lane = c & 31;

    for (int idx = c; idx < Cdim * 128; idx += 256) {
        int r = idx >> 7, k = idx & 127;
        wsm[r * K3_PITCH + k] = Wcc[(size_t)r * Cdim + k];
    }
    float wreg[128];
    {
        const float4* wrow4 = (const float4*)(Wcc + (size_t)c * Cdim + 128);
        #pragma unroll
        for (int j = 0; j < 32; j++) {
            float4 v = wrow4[j];
            wreg[4*j+0] = v.x; wreg[4*j+1] = v.y;
            wreg[4*j+2] = v.z; wreg[4*j+3] = v.w;
        }
    }
    float cp = 0.f;
    float gC = lncg[c], bC = lncb[c];
    const float2* wr2 = (const float2*)(wsm + c * K3_PITCH);
    __nv_bfloat16* ph = (__nv_bfloat16*)g_Abf_hi4;
    __nv_bfloat16* pl = (__nv_bfloat16*)g_Abf_lo4;
    __syncthreads();

    for (int t = 0; t < Tdim; t++) {
        int bt = b * Tdim + t;
        float s1 = cp, s2 = cp * cp;
        #pragma unroll
        for (int o = 16; o; o >>= 1) {
            s1 += __shfl_xor_sync(0xffffffffu, s1, o);
            s2 += __shfl_xor_sync(0xffffffffu, s2, o);
        }
        if (lane == 0) { sh[w] = s1; sh[8 + w] = s2; }
        __syncthreads();
        float t1 = 0.f, t2 = 0.f;
        #pragma unroll
        for (int j = 0; j < 8; j++) { t1 += sh[j]; t2 += sh[8 + j]; }
        float mu  = t1 * (1.f / Cdim);
        float var = t2 * (1.f / Cdim) - mu * mu;
        float inv = rsqrtf(var + LN_EPSF);
        lnc[c] = (cp - mu) * inv * gC + bC;
        __syncthreads();
        const float2* l2 = (const float2*)lnc;
        float a0 = 0.f, a1 = 0.f, a2 = 0.f, a3 = 0.f;
        #pragma unroll
        for (int j = 0; j < 64; j += 4) {
            float2 w0 = wr2[j],   l0 = l2[j];
            float2 w1 = wr2[j+1], l1 = l2[j+1];
            float2 w2 = wr2[j+2], l2v = l2[j+2];
            float2 w3 = wr2[j+3], l3 = l2[j+3];
            a0 = fmaf(w0.x, l0.x,  fmaf(w0.y, l0.y,  a0));
            a1 = fmaf(w1.x, l1.x,  fmaf(w1.y, l1.y,  a1));
            a2 = fmaf(w2.x, l2v.x, fmaf(w2.y, l2v.y, a2));
            a3 = fmaf(w3.x, l3.x,  fmaf(w3.y, l3.y,  a3));
        }
        #pragma unroll
        for (int j = 0; j < 128; j += 4) {
            a0 = fmaf(wreg[j+0], lnc[128 + j + 0], a0);
            a1 = fmaf(wreg[j+1], lnc[128 + j + 1], a1);
            a2 = fmaf(wreg[j+2], lnc[128 + j + 2], a2);
            a3 = fmaf(wreg[j+3], lnc[128 + j + 3], a3);
        }
        float acc = g_Lu[bt * Cdim + c] + (a0 + a1) + (a2 + a3);
        float aa  = fabsf(acc) - LAMf;
        float shr = aa > 0.f ? copysignf(aa, acc) : 0.f;
        shr_sm[c] = shr;
        float myv = fabsf(shr); int myi = c;
        #pragma unroll
        for (int k = 0; k < TOPKK; k++) {
            float mv = myv; int mi = myi;
            #pragma unroll
            for (int o = 16; o; o >>= 1) {
                float ov = __shfl_xor_sync(0xffffffffu, mv, o);
                int   oi = __shfl_xor_sync(0xffffffffu, mi, o);
                if (ov > mv || (ov == mv && oi < mi)) { mv = ov; mi = oi; }
            }
            if (lane == 0) { cwv[w * 8 + k] = mv; cwi[w * 8 + k] = mi; }
            if (myi == mi) myv = -1.f;
        }
        __syncthreads();
        if (w == 0) {
            float v0 = cwv[lane], v1 = cwv[32 + lane];
            int   i0 = cwi[lane], i1 = cwi[32 + lane];
            #pragma unroll
            for (int k = 0; k < TOPKK; k++) {
                float bv; int bi;
                if (v0 > v1 || (v0 == v1 && i0 < i1)) { bv = v0; bi = i0; }
                else                                   { bv = v1; bi = i1; }
                #pragma unroll
                for (int o = 16; o; o >>= 1) {
                    float ov = __shfl_xor_sync(0xffffffffu, bv, o);
                    int   oi = __shfl_xor_sync(0xffffffffu, bi, o);
                    if (ov > bv || (ov == bv && oi < bi)) { bv = ov; bi = oi; }
                }
                if (lane == 0) {
                    float sv = shr_sm[bi];
                    t8v[k] = sv; t8i[k] = bi;
                    g_aidx[bt * TOPKK + k] = bi;
                    g_aval[bt * TOPKK + k] = sv;
                }
                if (i0 == bi) v0 = -1.f;
                if (i1 == bi) v1 = -1.f;
            }
        }
        __syncthreads();
        float ac = 0.f;
        #pragma unroll
        for (int j = 0; j < TOPKK; j++)
            if (t8i[j] == c) ac = t8v[j];
        float vv = valid[bt];
        float cn = RHOf * cp + (1.f - RHOf) * ac;
        cp = vv * cn + (1.f - vv) * cp;
        g_ct[bt * Cdim + c] = cp;
        g_A[(size_t)bt * AP + Mdim + c] = cp;
        bf_split(cp, ph + bt * 768 + 512 + c, pl + bt * 768 + 512 + c);
    }
}

// ---------------- K4: pipelined cand GEMM, split u-part / c-part -----------
#define SOFF_A 0            // 4 x 20480: hi0, lo0, hi1, lo1
#define SOFF_W_HI 81920
#define SOFF_W_LO 87040
#define SOFF_BIAS 92160
#define K4_SMEM   92416
#define APITCH 80   // bytes per smem A/W row (32 bf16 + 8 pad)

__device__ __forceinline__ void stage_A(uint32_t sb, int buf, int k0, int tid) {
    uint32_t hbase = sb + SOFF_A + buf * 40960;
    uint32_t lbase = hbase + 20480;
    #pragma unroll
    for (int i = 0; i < 4; i++) {
        int s = tid + i * 256;
        int row = s >> 2, qq = s & 3;
        size_t soff = ((size_t)row * 768 + k0) * 2 + qq * 16;
        cpasync16(hbase + row * APITCH + qq * 16, (const char*)g_Abf_hi4 + soff);
        cpasync16(lbase + row * APITCH + qq * 16, (const char*)g_Abf_lo4 + soff);
    }
}
__device__ __forceinline__ void ldW_s(const float* __restrict__ W, int sw,
                                      int n0, int k0, int tid, float4* w) {
    #pragma unroll
    for (int i = 0; i < 2; i++) {
        int s = tid + i * 256;
        int row = s >> 3, c4 = (s & 7) * 4;
        w[i] = *(const float4*)(W + (size_t)(n0 + row) * sw + k0 + c4);
    }
}
__device__ __forceinline__ void storeW_smem(char* sm, int tid, const float4* wreg) {
    #pragma unroll
    for (int i = 0; i < 2; i++) {
        int s = tid + i * 256;
        int row = s >> 3, c4 = (s & 7) * 4;
        float4 v = wreg[i];
        __nv_bfloat16 h0 = __float2bfloat16_rn(v.x), h1 = __float2bfloat16_rn(v.y);
        __nv_bfloat16 h2 = __float2bfloat16_rn(v.z), h3 = __float2bfloat16_rn(v.w);
        uint2 hi, lo;
        hi.x = (uint32_t)__bfloat16_as_ushort(h0) | ((uint32_t)__bfloat16_as_ushort(h1) << 16);
        hi.y = (uint32_t)__bfloat16_as_ushort(h2) | ((uint32_t)__bfloat16_as_ushort(h3) << 16);
        __nv_bfloat16 l0 = __float2bfloat16_rn(v.x - __bfloat162float(h0));
        __nv_bfloat16 l1 = __float2bfloat16_rn(v.y - __bfloat162float(h1));
        __nv_bfloat16 l2 = __float2bfloat16_rn(v.z - __bfloat162float(h2));
        __nv_bfloat16 l3 = __float2bfloat16_rn(v.w - __bfloat162float(h3));
        lo.x = (uint32_t)__bfloat16_as_ushort(l0) | ((uint32_t)__bfloat16_as_ushort(l1) << 16);
        lo.y = (uint32_t)__bfloat16_as_ushort(l2) | ((uint32_t)__bfloat16_as_ushort(l3) << 16);
        *(uint2*)(sm + SOFF_W_HI + row * APITCH + c4 * 2) = hi;
        *(uint2*)(sm + SOFF_W_LO + row * APITCH + c4 * 2) = lo;
    }
}
__device__ __forceinline__ void k4_compute(uint32_t sb, int buf,
                                           const uint32_t* aoff, const uint32_t* boff,
                                           float acc[4][4][4]) {
    uint32_t abh = sb + SOFF_A + buf * 40960;
    uint32_t abl = abh + 20480;
    #pragma unroll
    for (int kh = 0; kh < 2; kh++) {
        uint32_t ah[4][4], al[4][4];
        #pragma unroll
        for (int mt = 0; mt < 4; mt++) {
            ldsm_x4(ah[mt], abh + aoff[mt] + kh * 32);
            ldsm_x4(al[mt], abl + aoff[mt] + kh * 32);
        }
        #pragma unroll
        for (int np = 0; np < 2; np++) {
            uint32_t bh[4], bl[4];
            ldsm_x4(bh, sb + SOFF_W_HI + boff[np] + kh * 32);
            ldsm_x4(bl, sb + SOFF_W_LO + boff[np] + kh * 32);
            #pragma unroll
            for (int h = 0; h < 2; h++) {
                #pragma unroll
                for (int mt = 0; mt < 4; mt++)
                    mma_bf16(acc[mt][np * 2 + h], ah[mt], bh[h * 2], bh[h * 2 + 1]);
                #pragma unroll
                for (int mt = 0; mt < 4; mt++)
                    mma_bf16(acc[mt][np * 2 + h], ah[mt], bl[h * 2], bl[h * 2 + 1]);
                #pragma unroll
                for (int mt = 0; mt < 4; mt++)
                    mma_bf16(acc[mt][np * 2 + h], al[mt], bh[h * 2], bh[h * 2 + 1]);
            }
        }
    }
}
__device__ __forceinline__ void k4_offsets(int wm, int wn, int lane,
                                           uint32_t* aoff, uint32_t* boff) {
    #pragma unroll
    for (int mt = 0; mt < 4; mt++)
        aoff[mt] = (uint32_t)((wm * 64 + mt * 16 + (lane & 15)) * APITCH + (lane >> 4) * 16);
    #pragma unroll
    for (int np = 0; np < 2; np++)
        boff[np] = (uint32_t)((wn * 32 + np * 16 + (lane & 7) + ((lane >> 4) << 3)) * APITCH
                              + ((lane >> 3) & 1) * 16);
}

__global__ void __launch_bounds__(256, 2)
k4a_mma(const float* __restrict__ Wu) {
    extern __shared__ char sm[];
    uint32_t sb = smem_u32(sm);
    int tid = threadIdx.x, wid = tid >> 5, lane = tid & 31;
    int wm = wid & 3, wn = wid >> 2;
    int n0 = blockIdx.x * 64;

    float acc[4][4][4];
    #pragma unroll
    for (int i = 0; i < 4; i++)
        #pragma unroll
        for (int j = 0; j < 4; j++)
            #pragma unroll
            for (int k = 0; k < 4; k++) acc[i][j][k] = 0.f;
    uint32_t aoff[4], boff[2];
    k4_offsets(wm, wn, lane, aoff, boff);

    stage_A(sb, 0, 0, tid);
    asm volatile("cp.async.commit_group;" ::: "memory");
    float4 wreg[2];
    ldW_s(Wu, 512, n0, 0, tid, wreg);

    for (int q = 0; q < 16; q++) {
        int buf = q & 1;
        __syncthreads();
        storeW_smem(sm, tid, wreg);
        if (q + 1 < 16) {
            stage_A(sb, buf ^ 1, (q + 1) * 32, tid);
            asm volatile("cp.async.commit_group;" ::: "memory");
            ldW_s(Wu, 512, n0, (q + 1) * 32, tid, wreg);
            asm volatile("cp.async.wait_group 1;" ::: "memory");
        } else {
            asm volatile("cp.async.wait_group 0;" ::: "memory");
        }
        __syncthreads();
        k4_compute(sb, buf, aoff, boff, acc);
    }
    #pragma unroll
    for (int mt = 0; mt < 4; mt++) {
        int row = wm * 64 + mt * 16 + (lane >> 2);
        #pragma unroll
        for (int nf = 0; nf < 4; nf++) {
            int cl = wn * 32 + nf * 8 + (lane & 3) * 2;
            *(float2*)(g_cand + (size_t)row * MC + n0 + cl)       = make_float2(acc[mt][nf][0], acc[mt][nf][1]);
            *(float2*)(g_cand + (size_t)(row + 8) * MC + n0 + cl) = make_float2(acc[mt][nf][2], acc[mt][nf][3]);
        }
    }
}

__global__ void __launch_bounds__(256, 2)
k4b_mma(const float* __restrict__ Wc,
        const float* __restrict__ bu, const float* __restrict__ bc) {
    extern __shared__ char sm[];
    uint32_t sb = smem_u32(sm);
    int tid = threadIdx.x, wid = tid >> 5, lane = tid & 31;
    int wm = wid & 3, wn = wid >> 2;
    int n0 = blockIdx.x * 64;

    if (tid < 64) ((float*)(sm + SOFF_BIAS))[tid] = bu[n0 + tid] + bc[n0 + tid];

    uint32_t aoff[4], boff[2];
    k4_offsets(wm, wn, lane, aoff, boff);

    stage_A(sb, 0, 512, tid);
    asm volatile("cp.async.commit_group;" ::: "memory");
    float4 wreg[2];
    ldW_s(Wc, 256, n0, 0, tid, wreg);

    float acc[4][4][4];
    #pragma unroll
    for (int mt = 0; mt < 4; mt++) {
        int row = wm * 64 + mt * 16 + (lane >> 2);
        #pragma unroll
        for (int nf = 0; nf < 4; nf++) {
            int cl = wn * 32 + nf * 8 + (lane & 3) * 2;
            float2 p0 = *(const float2*)(g_cand + (size_t)row * MC + n0 + cl);
            float2 p1 = *(const float2*)(g_cand + (size_t)(row + 8) * MC + n0 + cl);
            acc[mt][nf][0] = p0.x; acc[mt][nf][1] = p0.y;
            acc[mt][nf][2] = p1.x; acc[mt][nf][3] = p1.y;
        }
    }

    for (int q = 0; q < 8; q++) {
        int buf = q & 1;
        __syncthreads();
        storeW_smem(sm, tid, wreg);
        if (q + 1 < 8) {
            stage_A(sb, buf ^ 1, 512 + (q + 1) * 32, tid);
            asm volatile("cp.async.commit_group;" ::: "memory");
            ldW_s(Wc, 256, n0, (q + 1) * 32, tid, wreg);
            asm volatile("cp.async.wait_group 1;" ::: "memory");
        } else {
            asm volatile("cp.async.wait_group 0;" ::: "memory");
        }
        __syncthreads();
        k4_compute(sb, buf, aoff, boff, acc);
    }
    const float* bias = (const float*)(sm + SOFF_BIAS);
    #pragma unroll
    for (int mt = 0; mt < 4; mt++) {
        int row = wm * 64 + mt * 16 + (lane >> 2);
        #pragma unroll
        for (int nf = 0; nf < 4; nf++) {
            int cl = wn * 32 + nf * 8 + (lane & 3) * 2;
            float b0 = bias[cl], b1 = bias[cl + 1];
            float2 v0 = make_float2(acc[mt][nf][0] + b0, acc[mt][nf][1] + b1);
            float2 v1 = make_float2(acc[mt][nf][2] + b0, acc[mt][nf][3] + b1);
            *(float2*)(g_cand + (size_t)row * MC + n0 + cl)       = v0;
            *(float2*)(g_cand + (size_t)(row + 8) * MC + n0 + cl) = v1;
        }
    }
}

// ---------------- K5: D0 init + barrier reset ------------------------------
__global__ void k5_dinit(const float* __restrict__ base) {
    __shared__ float sh[8];
    int c = blockIdx.x, tid = threadIdx.x;  // 128 threads
    if (c < Bdim && tid == 0) g_bar[c] = 0;
    float s = 0.f;
    for (int m = tid; m < Mdim; m += 128) {
        float v = base[(size_t)m * Cdim + c];
        s += v * v;
    }
    float stot = blockReduceSum(s, sh);
    float inv = 1.f / fmaxf(sqrtf(stot), EPSF);
    for (int b = 0; b < Bdim; b++)
        for (int m = tid; m < Mdim; m += 128)
            g_D[0][((size_t)b * Cdim + c) * Mdim + m] = base[(size_t)m * Cdim + c] * inv;
}

// ---------------- K6: persistent steps (proven R11 body) + fused output ----
__global__ void __launch_bounds__(256, 2)
k_steps(const float* __restrict__ u, const float* __restrict__ valid,
        const float* __restrict__ Wg, const float* __restrict__ bg,
        float* __restrict__ out) {
    __shared__ float sh[8];
    __shared__ float rsh[Mdim];
    __shared__ float ctsh[Cdim];
    __shared__ float cnd[CPT][CPITCH];
    __shared__ int   aidx[TOPKK];
    __shared__ float aval[TOPKK];
    __shared__ float gsh;
    int tile = blockIdx.x, b = blockIdx.y, tid = threadIdx.x;
    int c0 = tile * CPT;
    int w = tid >> 5, lane = tid & 31;
    int cc = c0 + w;

    for (int t = 0; t < Tdim; t++) {
        int sbuf = t & 1;
        const float* Dsrc = g_D[sbuf];
        float*       Ddst = g_D[sbuf ^ 1];
        int bt = b * Tdim + t;
        const float* ur = u + (size_t)bt * Mdim;
        float vv = valid[bt];
        ctsh[tid] = g_ct[bt * Cdim + tid];
        if (tid < TOPKK) { aidx[tid] = g_aidx[bt * TOPKK + tid]; aval[tid] = g_aval[bt * TOPKK + tid]; }
        __syncthreads();
        float perr = 0.f, pg = 0.f;
        #pragma unroll
        for (int h = 0; h < 2; h++) {
            int m = tid + h * 256;
            float acc = ur[m];
            #pragma unroll
            for (int j = 0; j < TOPKK; j++)
                acc -= Dsrc[((size_t)b * Cdim + aidx[j]) * Mdim + m] * aval[j];
            rsh[m] = acc;
            perr += acc * acc;
            pg   += Wg[m] * ur[m];
        }
        pg += Wg[Mdim + tid] * ctsh[tid];
        // stage cand tile: coalesced float4 loads (c0..c0+7 contiguous 32B)
        const float* cb = g_cand + (size_t)bt * MC + c0;
        #pragma unroll
        for (int it = 0; it < 4; it++) {
            int i = tid + it * 256;
            int m = i >> 1, half = i & 1;
            float4 v = *(const float4*)(cb + (size_t)m * Cdim + half * 4);
            int jb = half * 4;
            cnd[jb + 0][m] = v.x; cnd[jb + 1][m] = v.y;
            cnd[jb + 2][m] = v.z; cnd[jb + 3][m] = v.w;
        }
        float errsum = blockReduceSum(perr, sh);
        float gsum   = blockReduceSum(pg, sh);
        if (tid == 0) {
            float err = sqrtf(errsum);
            float gp  = gsum + Wg[Mdim + Cdim] * err + bg[0];
            gsh = 1.f / (1.f + expf(-gp));
        }
        __syncthreads();
        float g = gsh;
        float av = 0.f;
        #pragma unroll
        for (int j = 0; j < TOPKK; j++)
            if (aidx[j] == cc) av = aval[j];
        const float* Dc = Dsrc + ((size_t)b * Cdim + cc) * Mdim;
        float*       Do = Ddst + ((size_t)b * Cdim + cc) * Mdim;
        float Dreg[16];
        float sl = 0.f, sc2 = 0.f, sx = 0.f;
        float dla = DLRf * av;
        #pragma unroll
        for (int k = 0; k < 16; k++) {
            int m = lane + 32 * k;
            float dd = Dc[m]; Dreg[k] = dd;
            float dl = fmaf(dla, rsh[m], dd);
            float cn = cnd[w][m];
            sl  = fmaf(dl, dl, sl);
            sc2 = fmaf(cn, cn, sc2);
            sx  = fmaf(dl, cn, sx);
        }
        #pragma unroll
        for (int o = 16; o; o >>= 1) {
            sl  += __shfl_xor_sync(0xffffffffu, sl,  o);
            sc2 += __shfl_xor_sync(0xffffffffu, sc2, o);
            sx  += __shfl_xor_sync(0xffffffffu, sx,  o);
        }
        float il  = 1.f / fmaxf(sqrtf(sl),  EPSF);
        float icn = 1.f / fmaxf(sqrtf(sc2), EPSF);
        float w1 = (1.f - g) * il, w2 = g * icn;
        float smix = w1 * w1 * sl + 2.f * w1 * w2 * sx + w2 * w2 * sc2;
        float imix = 1.f / fmaxf(sqrtf(smix), EPSF);
        float ctc = ctsh[cc];
        #pragma unroll
        for (int k = 0; k < 16; k++) {
            int m = lane + 32 * k;
            float dl  = fmaf(dla, rsh[m], Dreg[k]);
            float cn  = cnd[w][m];
            float mix = w1 * dl + w2 * cn;
            float dn  = vv * (mix * imix) + (1.f - vv) * Dreg[k];
            Do[m] = dn;
            cnd[w][m] = dn * ctc;
        }
        __syncthreads();
        float* zp = g_zpart + ((size_t)bt * NTILE + tile) * Mdim;
        for (int m = tid; m < Mdim; m += 256) {
            float z = 0.f;
            #pragma unroll
            for (int j = 0; j < CPT; j++) z += cnd[j][m];
            zp[m] = z;
        }
        __threadfence();
        __syncthreads();
        if (tid == 0) atomicAdd(&g_bar[b], 1u);
        if (t + 1 < Tdim) {
            if (tid == 0) {
                unsigned tgt = (unsigned)((t + 1) * NTILE);
                while (atomicAdd(&g_bar[b], 0u) < tgt) __nanosleep(32);
            }
            __syncthreads();
            __threadfence();
        }
    }
    // ---- fused output: wait for all tiles of batch b, reduce z for one bt --
    if (tid == 0) {
        while (atomicAdd(&g_bar[b], 0u) < (unsigned)(Tdim * NTILE)) __nanosleep(32);
    }
    __syncthreads();
    __threadfence();
    int obt = b * Tdim + tile;       // NTILE == Tdim == 32
    const float* zp = g_zpart + (size_t)obt * NTILE * Mdim;
    for (int m = tid; m < Mdim; m += 256) {
        float s = 0.f;
        #pragma unroll
        for (int j = 0; j < NTILE; j++) s += zp[(size_t)j * Mdim + m];
        out[obt * Mdim + m] = s;
    }
}

// ---------------- launch: proper e0-fork; k5/k2/k3 on s2 -------------------
extern "C" void kernel_launch(void* const* d_in, const int* in_sizes, int n_in,
                              void* d_out, int out_size) {
    const float* u       = (const float*)d_in[0];
    const float* valid   = (const float*)d_in[1];
    const float* base    = (const float*)d_in[2];
    const float* Wcu     = (const float*)d_in[3];
    const float* Wcc     = (const float*)d_in[4];
    const float* Wcand_u = (const float*)d_in[5];
    const float* bcand_u = (const float*)d_in[6];
    const float* Wcand_c = (const float*)d_in[7];
    const float* bcand_c = (const float*)d_in[8];
    const float* Wg      = (const float*)d_in[9];
    const float* bg      = (const float*)d_in[10];
    const float* lnug    = (const float*)d_in[11];
    const float* lnub    = (const float*)d_in[12];
    const float* lncg    = (const float*)d_in[13];
    const float* lncb    = (const float*)d_in[14];
    float* out = (float*)d_out;

    cudaFuncSetAttribute(k4a_mma, cudaFuncAttributeMaxDynamicSharedMemorySize, K4_SMEM);
    cudaFuncSetAttribute(k4b_mma, cudaFuncAttributeMaxDynamicSharedMemorySize, K4_SMEM);
    cudaFuncSetAttribute(k3_rec, cudaFuncAttributeMaxDynamicSharedMemorySize, K3W_SMEM);

    cudaStream_t s2;
    cudaStreamCreateWithFlags(&s2, cudaStreamNonBlocking);
    cudaEvent_t e0, e1, e2;
    cudaEventCreateWithFlags(&e0, cudaEventDisableTiming);
    cudaEventCreateWithFlags(&e1, cudaEventDisableTiming);
    cudaEventCreateWithFlags(&e2, cudaEventDisableTiming);

    // fork point: s2 joins the capture BEFORE any work is issued on it
    cudaEventRecord(e0, 0);
    cudaStreamWaitEvent(s2, e0, 0);

    // s2: D init (independent of k1)
    k5_dinit<<<Cdim, 128, 0, s2>>>(base);

    // main: LN(u) + u bf16 split (critical path head)
    k1_lnu<<<BT, 256>>>(u, lnug, lnub);
    cudaEventRecord(e1, 0);

    // s2: Lu projection + recurrence + c bf16 split (off main path)
    cudaStreamWaitEvent(s2, e1, 0);
    k2_lu <<<BT, 256, 0, s2>>>(Wcu);
    k3_rec<<<Bdim, 256, K3W_SMEM, s2>>>(Wcc, valid, lncg, lncb);
    cudaEventRecord(e2, s2);

    // main: u-part GEMM (overlaps k2+k3)
    k4a_mma<<<MC / 64, 256, K4_SMEM>>>(Wcand_u);

    // join, then c-part GEMM and the dictionary steps
    cudaStreamWaitEvent(0, e2, 0);
    k4b_mma<<<MC / 64, 256, K4_SMEM>>>(Wcand_c, bcand_u, bcand_c);
    k_steps<<<dim3(NTILE, Bdim), 256>>>(u, valid, Wg, bg, out);

    cudaEventDestroy(e0);
    cudaEventDestroy(e1);
    cudaEventDestroy(e2);
    cudaStreamDestroy(s2);
}

// round 15
// speedup vs baseline: 1.1722x; 1.1722x over previous
#include <cuda_runtime.h>
#include <cuda_bf16.h>
#include <cstdint>

#define Mdim 512
#define Cdim 256
#define Bdim 8
#define Tdim 32
#define BT 256            // B*T
#define MC 131072         // M*C
#define TOPKK 8
#define LAMf 0.05f
#define RHOf 0.9f
#define DLRf 0.03f
#define EPSF 1e-12f
#define LN_EPSF 1e-5f
#define AP 776            // padded A row pitch (floats)
#define NTILE 32          // C / 8 column tiles
#define CPT 8             // columns per tile
#define CPITCH 520        // smem cand pitch

// ---------------- scratch (device globals; no allocation allowed) ----------
__device__ float g_LNu[BT * Mdim];
__device__ float g_A[BT * AP];                     // [u(512) | c_t(256)] rows
__device__ float g_Lu[BT * Cdim];
__device__ float g_ct[BT * Cdim];
__device__ int   g_aidx[BT * TOPKK];
__device__ float g_aval[BT * TOPKK];
__device__ float g_cand[(size_t)BT * MC];          // 128 MiB cand scratch / partials
__device__ float g_D[2][Bdim * Cdim * Mdim];       // ping-pong dictionary [b][c][m]
__device__ float g_zpart[(size_t)BT * NTILE * Mdim];
__device__ unsigned g_bar[Bdim];                   // per-batch step barriers (k_steps)
__device__ uint4 g_Abf_hi4[BT * 768 * 2 / 16];     // A hi bf16 (16B-aligned)
__device__ uint4 g_Abf_lo4[BT * 768 * 2 / 16];     // A lo bf16

// ---------------- helpers --------------------------------------------------
__device__ __forceinline__ uint32_t smem_u32(const void* p) {
    uint32_t a;
    asm("{ .reg .u64 t; cvta.to.shared.u64 t, %1; cvt.u32.u64 %0, t; }" : "=r"(a) : "l"(p));
    return a;
}
__device__ __forceinline__ void ldsm_x4(uint32_t* r, uint32_t addr) {
    asm volatile("ldmatrix.sync.aligned.m8n8.x4.shared.b16 {%0,%1,%2,%3}, [%4];"
        : "=r"(r[0]), "=r"(r[1]), "=r"(r[2]), "=r"(r[3]) : "r"(addr));
}
__device__ __forceinline__ void mma_bf16(float* c, const uint32_t* a, uint32_t b0, uint32_t b1) {
    asm volatile("mma.sync.aligned.m16n8k16.row.col.f32.bf16.bf16.f32 "
        "{%0,%1,%2,%3}, {%4,%5,%6,%7}, {%8,%9}, {%0,%1,%2,%3};"
        : "+f"(c[0]), "+f"(c[1]), "+f"(c[2]), "+f"(c[3])
        : "r"(a[0]), "r"(a[1]), "r"(a[2]), "r"(a[3]), "r"(b0), "r"(b1));
}
__device__ __forceinline__ void cpasync16(uint32_t dst, const void* src) {
    asm volatile("cp.async.cg.shared.global [%0], [%1], 16;" :: "r"(dst), "l"(src));
}
__device__ __forceinline__ float blockReduceSum(float v, float* sh) {
    __syncthreads();
    #pragma unroll
    for (int o = 16; o; o >>= 1) v += __shfl_xor_sync(0xffffffffu, v, o);
    int w = threadIdx.x >> 5, l = threadIdx.x & 31;
    if (l == 0) sh[w] = v;
    __syncthreads();
    if (w == 0) {
        float x = (l < (int)(blockDim.x >> 5)) ? sh[l] : 0.f;
        #pragma unroll
        for (int o = 4; o; o >>= 1) x += __shfl_xor_sync(0xffffffffu, x, o);
        if (l == 0) sh[0] = x;
    }
    __syncthreads();
    return sh[0];
}
__device__ __forceinline__ void bf_split(float v, __nv_bfloat16* ph, __nv_bfloat16* pl) {
    __nv_bfloat16 h = __float2bfloat16_rn(v);
    *ph = h;
    *pl = __float2bfloat16_rn(v - __bfloat162float(h));
}

// ---------------- K1: LN(u), fill A u-part + bf16 u split ------------------
__global__ void k1_lnu(const float* __restrict__ u,
                       const float* __restrict__ g, const float* __restrict__ bb) {
    __shared__ float sh[8];
    int r = blockIdx.x, tid = threadIdx.x;
    const float* ur = u + (size_t)r * Mdim;
    float x0 = ur[tid], x1 = ur[tid + 256];
    float s = blockReduceSum(x0 + x1, sh);
    float mu = s * (1.f / Mdim);
    float d0 = x0 - mu, d1 = x1 - mu;
    float var = blockReduceSum(d0 * d0 + d1 * d1, sh) * (1.f / Mdim);
    float inv = rsqrtf(var + LN_EPSF);
    g_LNu[(size_t)r * Mdim + tid]       = d0 * inv * g[tid] + bb[tid];
    g_LNu[(size_t)r * Mdim + tid + 256] = d1 * inv * g[tid + 256] + bb[tid + 256];
    g_A[(size_t)r * AP + tid]       = x0;
    g_A[(size_t)r * AP + tid + 256] = x1;
    __nv_bfloat16* ph = (__nv_bfloat16*)g_Abf_hi4;
    __nv_bfloat16* pl = (__nv_bfloat16*)g_Abf_lo4;
    bf_split(x0, ph + r * 768 + tid,       pl + r * 768 + tid);
    bf_split(x1, ph + r * 768 + tid + 256, pl + r * 768 + tid + 256);
}

// ---------------- K2: Lu = LN(u) @ W_cu^T ---------------------------------
__global__ void k2_lu(const float* __restrict__ Wcu) {
    __shared__ float ln[Mdim];
    int r = blockIdx.x, c = threadIdx.x;
    ln[c]       = g_LNu[(size_t)r * Mdim + c];
    ln[c + 256] = g_LNu[(size_t)r * Mdim + c + 256];
    __syncthreads();
    const float4* wr = (const float4*)(Wcu + (size_t)c * Mdim);
    float a0 = 0.f, a1 = 0.f, a2 = 0.f, a3 = 0.f;
    #pragma unroll 4
    for (int i = 0; i < 128; i += 4) {
        float4 w0 = wr[i],   w1 = wr[i+1], w2 = wr[i+2], w3 = wr[i+3];
        a0 = fmaf(w0.x, ln[4*i+0], fmaf(w0.y, ln[4*i+1], fmaf(w0.z, ln[4*i+2], fmaf(w0.w, ln[4*i+3], a0))));
        a1 = fmaf(w1.x, ln[4*i+4], fmaf(w1.y, ln[4*i+5], fmaf(w1.z, ln[4*i+6], fmaf(w1.w, ln[4*i+7], a1))));
        a2 = fmaf(w2.x, ln[4*i+8], fmaf(w2.y, ln[4*i+9], fmaf(w2.z, ln[4*i+10], fmaf(w2.w, ln[4*i+11], a2))));
        a3 = fmaf(w3.x, ln[4*i+12], fmaf(w3.y, ln[4*i+13], fmaf(w3.z, ln[4*i+14], fmaf(w3.w, ln[4*i+15], a3))));
    }
    g_Lu[r * Cdim + c] = (a0 + a1) + (a2 + a3);
}

// ---------------- K3: recurrence, Wcc resident (smem+regs) + c bf16 split --
#define K3_PITCH 130
#define K3W_SMEM (Cdim * K3_PITCH * 4)      // 133120 bytes

__global__ void __launch_bounds__(256, 1)
k3_rec(const float* __restrict__ Wcc, const float* __restrict__ valid,
       const float* __restrict__ lncg, const float* __restrict__ lncb) {
    extern __shared__ float wsm[];          // [256][K3_PITCH]
    __shared__ float sh[16];
    __shared__ float lnc[Cdim];
    __shared__ float shr_sm[Cdim];
    __shared__ float cwv[64];
    __shared__ int   cwi[64];
    __shared__ float t8v[TOPKK];
    __shared__ int   t8i[TOPKK];
    int b = blockIdx.x, c = threadIdx.x;
    int w = c >> 5, lane = c & 31;

    for (int idx = c; idx < Cdim * 128; idx += 256) {
        int r = idx >> 7, k = idx & 127;
        wsm[r * K3_PITCH + k] = Wcc[(size_t)r * Cdim + k];
    }
    float wreg[128];
    {
        const float4* wrow4 = (const float4*)(Wcc + (size_t)c * Cdim + 128);
        #pragma unroll
        for (int j = 0; j < 32; j++) {
            float4 v = wrow4[j];
            wreg[4*j+0] = v.x; wreg[4*j+1] = v.y;
            wreg[4*j+2] = v.z; wreg[4*j+3] = v.w;
        }
    }
    float cp = 0.f;
    float gC = lncg[c], bC = lncb[c];
    const float2* wr2 = (const float2*)(wsm + c * K3_PITCH);
    __nv_bfloat16* ph = (__nv_bfloat16*)g_Abf_hi4;
    __nv_bfloat16* pl = (__nv_bfloat16*)g_Abf_lo4;
    __syncthreads();

    for (int t = 0; t < Tdim; t++) {
        int bt = b * Tdim + t;
        float s1 = cp, s2 = cp * cp;
        #pragma unroll
        for (int o = 16; o; o >>= 1) {
            s1 += __shfl_xor_sync(0xffffffffu, s1, o);
            s2 += __shfl_xor_sync(0xffffffffu, s2, o);
        }
        if (lane == 0) { sh[w] = s1; sh[8 + w] = s2; }
        __syncthreads();
        float t1 = 0.f, t2 = 0.f;
        #pragma unroll
        for (int j = 0; j < 8; j++) { t1 += sh[j]; t2 += sh[8 + j]; }
        float mu  = t1 * (1.f / Cdim);
        float var = t2 * (1.f / Cdim) - mu * mu;
        float inv = rsqrtf(var + LN_EPSF);
        lnc[c] = (cp - mu) * inv * gC + bC;
        __syncthreads();
        const float2* l2 = (const float2*)lnc;
        float a0 = 0.f, a1 = 0.f, a2 = 0.f, a3 = 0.f;
        #pragma unroll
        for (int j = 0; j < 64; j += 4) {
            float2 w0 = wr2[j],   l0 = l2[j];
            float2 w1 = wr2[j+1], l1 = l2[j+1];
            float2 w2 = wr2[j+2], l2v = l2[j+2];
            float2 w3 = wr2[j+3], l3 = l2[j+3];
            a0 = fmaf(w0.x, l0.x,  fmaf(w0.y, l0.y,  a0));
            a1 = fmaf(w1.x, l1.x,  fmaf(w1.y, l1.y,  a1));
            a2 = fmaf(w2.x, l2v.x, fmaf(w2.y, l2v.y, a2));
            a3 = fmaf(w3.x, l3.x,  fmaf(w3.y, l3.y,  a3));
        }
        #pragma unroll
        for (int j = 0; j < 128; j += 4) {
            a0 = fmaf(wreg[j+0], lnc[128 + j + 0], a0);
            a1 = fmaf(wreg[j+1], lnc[128 + j + 1], a1);
            a2 = fmaf(wreg[j+2], lnc[128 + j + 2], a2);
            a3 = fmaf(wreg[j+3], lnc[128 + j + 3], a3);
        }
        float acc = g_Lu[bt * Cdim + c] + (a0 + a1) + (a2 + a3);
        float aa  = fabsf(acc) - LAMf;
        float shr = aa > 0.f ? copysignf(aa, acc) : 0.f;
        shr_sm[c] = shr;
        float myv = fabsf(shr); int myi = c;
        #pragma unroll
        for (int k = 0; k < TOPKK; k++) {
            float mv = myv; int mi = myi;
            #pragma unroll
            for (int o = 16; o; o >>= 1) {
                float ov = __shfl_xor_sync(0xffffffffu, mv, o);
                int   oi = __shfl_xor_sync(0xffffffffu, mi, o);
                if (ov > mv || (ov == mv && oi < mi)) { mv = ov; mi = oi; }
            }
            if (lane == 0) { cwv[w * 8 + k] = mv; cwi[w * 8 + k] = mi; }
            if (myi == mi) myv = -1.f;
        }
        __syncthreads();
        if (w == 0) {
            float v0 = cwv[lane], v1 = cwv[32 + lane];
            int   i0 = cwi[lane], i1 = cwi[32 + lane];
            #pragma unroll
            for (int k = 0; k < TOPKK; k++) {
                float bv; int bi;
                if (v0 > v1 || (v0 == v1 && i0 < i1)) { bv = v0; bi = i0; }
                else                                   { bv = v1; bi = i1; }
                #pragma unroll
                for (int o = 16; o; o >>= 1) {
                    float ov = __shfl_xor_sync(0xffffffffu, bv, o);
                    int   oi = __shfl_xor_sync(0xffffffffu, bi, o);
                    if (ov > bv || (ov == bv && oi < bi)) { bv = ov; bi = oi; }
                }
                if (lane == 0) {
                    float sv = shr_sm[bi];
                    t8v[k] = sv; t8i[k] = bi;
                    g_aidx[bt * TOPKK + k] = bi;
                    g_aval[bt * TOPKK + k] = sv;
                }
                if (i0 == bi) v0 = -1.f;
                if (i1 == bi) v1 = -1.f;
            }
        }
        __syncthreads();
        float ac = 0.f;
        #pragma unroll
        for (int j = 0; j < TOPKK; j++)
            if (t8i[j] == c) ac = t8v[j];
        float vv = valid[bt];
        float cn = RHOf * cp + (1.f - RHOf) * ac;
        cp = vv * cn + (1.f - vv) * cp;
        g_ct[bt * Cdim + c] = cp;
        g_A[(size_t)bt * AP + Mdim + c] = cp;
        bf_split(cp, ph + bt * 768 + 512 + c, pl + bt * 768 + 512 + c);
    }
}

// ---------------- K4: pipelined cand GEMM, split u-part / c-part -----------
#define SOFF_A 0            // 4 x 20480: hi0, lo0, hi1, lo1
#define SOFF_W_HI 81920
#define SOFF_W_LO 87040
#define SOFF_BIAS 92160
#define K4_SMEM   92416
#define APITCH 80   // bytes per smem A/W row (32 bf16 + 8 pad)

__device__ __forceinline__ void stage_A(uint32_t sb, int buf, int k0, int tid) {
    uint32_t hbase = sb + SOFF_A + buf * 40960;
    uint32_t lbase = hbase + 20480;
    #pragma unroll
    for (int i = 0; i < 4; i++) {
        int s = tid + i * 256;
        int row = s >> 2, qq = s & 3;
        size_t soff = ((size_t)row * 768 + k0) * 2 + qq * 16;
        cpasync16(hbase + row * APITCH + qq * 16, (const char*)g_Abf_hi4 + soff);
        cpasync16(lbase + row * APITCH + qq * 16, (const char*)g_Abf_lo4 + soff);
    }
}
__device__ __forceinline__ void ldW_s(const float* __restrict__ W, int sw,
                                      int n0, int k0, int tid, float4* w) {
    #pragma unroll
    for (int i = 0; i < 2; i++) {
        int s = tid + i * 256;
        int row = s >> 3, c4 = (s & 7) * 4;
        w[i] = *(const float4*)(W + (size_t)(n0 + row) * sw + k0 + c4);
    }
}
__device__ __forceinline__ void storeW_smem(char* sm, int tid, const float4* wreg) {
    #pragma unroll
    for (int i = 0; i < 2; i++) {
        int s = tid + i * 256;
        int row = s >> 3, c4 = (s & 7) * 4;
        float4 v = wreg[i];
        __nv_bfloat16 h0 = __float2bfloat16_rn(v.x), h1 = __float2bfloat16_rn(v.y);
        __nv_bfloat16 h2 = __float2bfloat16_rn(v.z), h3 = __float2bfloat16_rn(v.w);
        uint2 hi, lo;
        hi.x = (uint32_t)__bfloat16_as_ushort(h0) | ((uint32_t)__bfloat16_as_ushort(h1) << 16);
        hi.y = (uint32_t)__bfloat16_as_ushort(h2) | ((uint32_t)__bfloat16_as_ushort(h3) << 16);
        __nv_bfloat16 l0 = __float2bfloat16_rn(v.x - __bfloat162float(h0));
        __nv_bfloat16 l1 = __float2bfloat16_rn(v.y - __bfloat162float(h1));
        __nv_bfloat16 l2 = __float2bfloat16_rn(v.z - __bfloat162float(h2));
        __nv_bfloat16 l3 = __float2bfloat16_rn(v.w - __bfloat162float(h3));
        lo.x = (uint32_t)__bfloat16_as_ushort(l0) | ((uint32_t)__bfloat16_as_ushort(l1) << 16);
        lo.y = (uint32_t)__bfloat16_as_ushort(l2) | ((uint32_t)__bfloat16_as_ushort(l3) << 16);
        *(uint2*)(sm + SOFF_W_HI + row * APITCH + c4 * 2) = hi;
        *(uint2*)(sm + SOFF_W_LO + row * APITCH + c4 * 2) = lo;
    }
}
__device__ __forceinline__ void k4_compute(uint32_t sb, int buf,
                                           const uint32_t* aoff, const uint32_t* boff,
                                           float acc[4][4][4]) {
    uint32_t abh = sb + SOFF_A + buf * 40960;
    uint32_t abl = abh + 20480;
    #pragma unroll
    for (int kh = 0; kh < 2; kh++) {
        uint32_t ah[4][4], al[4][4];
        #pragma unroll
        for (int mt = 0; mt < 4; mt++) {
            ldsm_x4(ah[mt], abh + aoff[mt] + kh * 32);
            ldsm_x4(al[mt], abl + aoff[mt] + kh * 32);
        }
        #pragma unroll
        for (int np = 0; np < 2; np++) {
            uint32_t bh[4], bl[4];
            ldsm_x4(bh, sb + SOFF_W_HI + boff[np] + kh * 32);
            ldsm_x4(bl, sb + SOFF_W_LO + boff[np] + kh * 32);
            #pragma unroll
            for (int h = 0; h < 2; h++) {
                #pragma unroll
                for (int mt = 0; mt < 4; mt++)
                    mma_bf16(acc[mt][np * 2 + h], ah[mt], bh[h * 2], bh[h * 2 + 1]);
                #pragma unroll
                for (int mt = 0; mt < 4; mt++)
                    mma_bf16(acc[mt][np * 2 + h], ah[mt], bl[h * 2], bl[h * 2 + 1]);
                #pragma unroll
                for (int mt = 0; mt < 4; mt++)
                    mma_bf16(acc[mt][np * 2 + h], al[mt], bh[h * 2], bh[h * 2 + 1]);
            }
        }
    }
}
__device__ __forceinline__ void k4_offsets(int wm, int wn, int lane,
                                           uint32_t* aoff, uint32_t* boff) {
    #pragma unroll
    for (int mt = 0; mt < 4; mt++)
        aoff[mt] = (uint32_t)((wm * 64 + mt * 16 + (lane & 15)) * APITCH + (lane >> 4) * 16);
    #pragma unroll
    for (int np = 0; np < 2; np++)
        boff[np] = (uint32_t)((wn * 32 + np * 16 + (lane & 7) + ((lane >> 4) << 3)) * APITCH
                              + ((lane >> 3) & 1) * 16);
}

__global__ void __launch_bounds__(256, 2)
k4a_mma(const float* __restrict__ Wu) {
    extern __shared__ char sm[];
    uint32_t sb = smem_u32(sm);
    int tid = threadIdx.x, wid = tid >> 5, lane = tid & 31;
    int wm = wid & 3, wn = wid >> 2;
    int n0 = blockIdx.x * 64;

    float acc[4][4][4];
    #pragma unroll
    for (int i = 0; i < 4; i++)
        #pragma unroll
        for (int j = 0; j < 4; j++)
            #pragma unroll
            for (int k = 0; k < 4; k++) acc[i][j][k] = 0.f;
    uint32_t aoff[4], boff[2];
    k4_offsets(wm, wn, lane, aoff, boff);

    stage_A(sb, 0, 0, tid);
    asm volatile("cp.async.commit_group;" ::: "memory");
    float4 wreg[2];
    ldW_s(Wu, 512, n0, 0, tid, wreg);

    for (int q = 0; q < 16; q++) {
        int buf = q & 1;
        __syncthreads();
        storeW_smem(sm, tid, wreg);
        if (q + 1 < 16) {
            stage_A(sb, buf ^ 1, (q + 1) * 32, tid);
            asm volatile("cp.async.commit_group;" ::: "memory");
            ldW_s(Wu, 512, n0, (q + 1) * 32, tid, wreg);
            asm volatile("cp.async.wait_group 1;" ::: "memory");
        } else {
            asm volatile("cp.async.wait_group 0;" ::: "memory");
        }
        __syncthreads();
        k4_compute(sb, buf, aoff, boff, acc);
    }
    #pragma unroll
    for (int mt = 0; mt < 4; mt++) {
        int row = wm * 64 + mt * 16 + (lane >> 2);
        #pragma unroll
        for (int nf = 0; nf < 4; nf++) {
            int cl = wn * 32 + nf * 8 + (lane & 3) * 2;
            *(float2*)(g_cand + (size_t)row * MC + n0 + cl)       = make_float2(acc[mt][nf][0], acc[mt][nf][1]);
            *(float2*)(g_cand + (size_t)(row + 8) * MC + n0 + cl) = make_float2(acc[mt][nf][2], acc[mt][nf][3]);
        }
    }
}

__global__ void __launch_bounds__(256, 2)
k4b_mma(const float* __restrict__ Wc,
        const float* __restrict__ bu, const float* __restrict__ bc) {
    extern __shared__ char sm[];
    uint32_t sb = smem_u32(sm);
    int tid = threadIdx.x, wid = tid >> 5, lane = tid & 31;
    int wm = wid & 3, wn = wid >> 2;
    int n0 = blockIdx.x * 64;

    if (tid < 64) ((float*)(sm + SOFF_BIAS))[tid] = bu[n0 + tid] + bc[n0 + tid];

    uint32_t aoff[4], boff[2];
    k4_offsets(wm, wn, lane, aoff, boff);

    stage_A(sb, 0, 512, tid);
    asm volatile("cp.async.commit_group;" ::: "memory");
    float4 wreg[2];
    ldW_s(Wc, 256, n0, 0, tid, wreg);

    float acc[4][4][4];
    #pragma unroll
    for (int mt = 0; mt < 4; mt++) {
        int row = wm * 64 + mt * 16 + (lane >> 2);
        #pragma unroll
        for (int nf = 0; nf < 4; nf++) {
            int cl = wn * 32 + nf * 8 + (lane & 3) * 2;
            float2 p0 = *(const float2*)(g_cand + (size_t)row * MC + n0 + cl);
            float2 p1 = *(const float2*)(g_cand + (size_t)(row + 8) * MC + n0 + cl);
            acc[mt][nf][0] = p0.x; acc[mt][nf][1] = p0.y;
            acc[mt][nf][2] = p1.x; acc[mt][nf][3] = p1.y;
        }
    }

    for (int q = 0; q < 8; q++) {
        int buf = q & 1;
        __syncthreads();
        storeW_smem(sm, tid, wreg);
        if (q + 1 < 8) {
            stage_A(sb, buf ^ 1, 512 + (q + 1) * 32, tid);
            asm volatile("cp.async.commit_group;" ::: "memory");
            ldW_s(Wc, 256, n0, (q + 1) * 32, tid, wreg);
            asm volatile("cp.async.wait_group 1;" ::: "memory");
        } else {
            asm volatile("cp.async.wait_group 0;" ::: "memory");
        }
        __syncthreads();
        k4_compute(sb, buf, aoff, boff, acc);
    }
    const float* bias = (const float*)(sm + SOFF_BIAS);
    #pragma unroll
    for (int mt = 0; mt < 4; mt++) {
        int row = wm * 64 + mt * 16 + (lane >> 2);
        #pragma unroll
        for (int nf = 0; nf < 4; nf++) {
            int cl = wn * 32 + nf * 8 + (lane & 3) * 2;
            float b0 = bias[cl], b1 = bias[cl + 1];
            float2 v0 = make_float2(acc[mt][nf][0] + b0, acc[mt][nf][1] + b1);
            float2 v1 = make_float2(acc[mt][nf][2] + b0, acc[mt][nf][3] + b1);
            *(float2*)(g_cand + (size_t)row * MC + n0 + cl)       = v0;
            *(float2*)(g_cand + (size_t)(row + 8) * MC + n0 + cl) = v1;
        }
    }
}

// ---------------- K5: D0 init + barrier reset ------------------------------
__global__ void k5_dinit(const float* __restrict__ base) {
    __shared__ float sh[8];
    int c = blockIdx.x, tid = threadIdx.x;  // 128 threads
    if (c < Bdim && tid == 0) g_bar[c] = 0;
    float s = 0.f;
    for (int m = tid; m < Mdim; m += 128) {
        float v = base[(size_t)m * Cdim + c];
        s += v * v;
    }
    float stot = blockReduceSum(s, sh);
    float inv = 1.f / fmaxf(sqrtf(stot), EPSF);
    for (int b = 0; b < Bdim; b++)
        for (int m = tid; m < Mdim; m += 128)
            g_D[0][((size_t)b * Cdim + c) * Mdim + m] = base[(size_t)m * Cdim + c] * inv;
}

// ---------------- K6: persistent steps (proven R11 body) + fused output ----
__global__ void __launch_bounds__(256, 2)
k_steps(const float* __restrict__ u, const float* __restrict__ valid,
        const float* __restrict__ Wg, const float* __restrict__ bg,
        float* __restrict__ out) {
    __shared__ float sh[8];
    __shared__ float rsh[Mdim];
    __shared__ float ctsh[Cdim];
    __shared__ float cnd[CPT][CPITCH];
    __shared__ int   aidx[TOPKK];
    __shared__ float aval[TOPKK];
    __shared__ float gsh;
    int tile = blockIdx.x, b = blockIdx.y, tid = threadIdx.x;
    int c0 = tile * CPT;
    int w = tid >> 5, lane = tid & 31;
    int cc = c0 + w;

    for (int t = 0; t < Tdim; t++) {
        int sbuf = t & 1;
        const float* Dsrc = g_D[sbuf];
        float*       Ddst = g_D[sbuf ^ 1];
        int bt = b * Tdim + t;
        const float* ur = u + (size_t)bt * Mdim;
        float vv = valid[bt];
        ctsh[tid] = g_ct[bt * Cdim + tid];
        if (tid < TOPKK) { aidx[tid] = g_aidx[bt * TOPKK + tid]; aval[tid] = g_aval[bt * TOPKK + tid]; }
        __syncthreads();
        float perr = 0.f, pg = 0.f;
        #pragma unroll
        for (int h = 0; h < 2; h++) {
            int m = tid + h * 256;
            float acc = ur[m];
            #pragma unroll
            for (int j = 0; j < TOPKK; j++)
                acc -= Dsrc[((size_t)b * Cdim + aidx[j]) * Mdim + m] * aval[j];
            rsh[m] = acc;
            perr += acc * acc;
            pg   += Wg[m] * ur[m];
        }
        pg += Wg[Mdim + tid] * ctsh[tid];
        // stage cand tile: coalesced float4 loads (c0..c0+7 contiguous 32B)
        const float* cb = g_cand + (size_t)bt * MC + c0;
        #pragma unroll
        for (int it = 0; it < 4; it++) {
            int i = tid + it * 256;
            int m = i >> 1, half = i & 1;
            float4 v = *(const float4*)(cb + (size_t)m * Cdim + half * 4);
            int jb = half * 4;
            cnd[jb + 0][m] = v.x; cnd[jb + 1][m] = v.y;
            cnd[jb + 2][m] = v.z; cnd[jb + 3][m] = v.w;
        }
        float errsum = blockReduceSum(perr, sh);
        float gsum   = blockReduceSum(pg, sh);
        if (tid == 0) {
            float err = sqrtf(errsum);
            float gp  = gsum + Wg[Mdim + Cdim] * err + bg[0];
            gsh = 1.f / (1.f + expf(-gp));
        }
        __syncthreads();
        float g = gsh;
        float av = 0.f;
        #pragma unroll
        for (int j = 0; j < TOPKK; j++)
            if (aidx[j] == cc) av = aval[j];
        const float* Dc = Dsrc + ((size_t)b * Cdim + cc) * Mdim;
        float*       Do = Ddst + ((size_t)b * Cdim + cc) * Mdim;
        float Dreg[16];
        float sl = 0.f, sc2 = 0.f, sx = 0.f;
        float dla = DLRf * av;
        #pragma unroll
        for (int k = 0; k < 16; k++) {
            int m = lane + 32 * k;
            float dd = Dc[m]; Dreg[k] = dd;
            float dl = fmaf(dla, rsh[m], dd);
            float cn = cnd[w][m];
            sl  = fmaf(dl, dl, sl);
            sc2 = fmaf(cn, cn, sc2);
            sx  = fmaf(dl, cn, sx);
        }
        #pragma unroll
        for (int o = 16; o; o >>= 1) {
            sl  += __shfl_xor_sync(0xffffffffu, sl,  o);
            sc2 += __shfl_xor_sync(0xffffffffu, sc2, o);
            sx  += __shfl_xor_sync(0xffffffffu, sx,  o);
        }
        float il  = 1.f / fmaxf(sqrtf(sl),  EPSF);
        float icn = 1.f / fmaxf(sqrtf(sc2), EPSF);
        float w1 = (1.f - g) * il, w2 = g * icn;
        float smix = w1 * w1 * sl + 2.f * w1 * w2 * sx + w2 * w2 * sc2;
        float imix = 1.f / fmaxf(sqrtf(smix), EPSF);
        float ctc = ctsh[cc];
        #pragma unroll
        for (int k = 0; k < 16; k++) {
            int m = lane + 32 * k;
            float dl  = fmaf(dla, rsh[m], Dreg[k]);
            float cn  = cnd[w][m];
            float mix = w1 * dl + w2 * cn;
            float dn  = vv * (mix * imix) + (1.f - vv) * Dreg[k];
            Do[m] = dn;
            cnd[w][m] = dn * ctc;
        }
        __syncthreads();
        float* zp = g_zpart + ((size_t)bt * NTILE + tile) * Mdim;
        for (int m = tid; m < Mdim; m += 256) {
            float z = 0.f;
            #pragma unroll
            for (int j = 0; j < CPT; j++) z += cnd[j][m];
            zp[m] = z;
        }
        __threadfence();
        __syncthreads();
        if (tid == 0) atomicAdd(&g_bar[b], 1u);
        if (t + 1 < Tdim) {
            if (tid == 0) {
                unsigned tgt = (unsigned)((t + 1) * NTILE);
                while (atomicAdd(&g_bar[b], 0u) < tgt) __nanosleep(32);
            }
            __syncthreads();
            __threadfence();
        }
    }
    // ---- fused output: wait for all tiles of batch b, reduce z for one bt --
    if (tid == 0) {
        while (atomicAdd(&g_bar[b], 0u) < (unsigned)(Tdim * NTILE)) __nanosleep(32);
    }
    __syncthreads();
    __threadfence();
    int obt = b * Tdim + tile;       // NTILE == Tdim == 32
    const float* zp = g_zpart + (size_t)obt * NTILE * Mdim;
    for (int m = tid; m < Mdim; m += 256) {
        float s = 0.f;
        #pragma unroll
        for (int j = 0; j < NTILE; j++) s += zp[(size_t)j * Mdim + m];
        out[obt * Mdim + m] = s;
    }
}

// ---------------- launch: R11 ordering + high-priority k3 stream -----------
extern "C" void kernel_launch(void* const* d_in, const int* in_sizes, int n_in,
                              void* d_out, int out_size) {
    const float* u       = (const float*)d_in[0];
    const float* valid   = (const float*)d_in[1];
    const float* base    = (const float*)d_in[2];
    const float* Wcu     = (const float*)d_in[3];
    const float* Wcc     = (const float*)d_in[4];
    const float* Wcand_u = (const float*)d_in[5];
    const float* bcand_u = (const float*)d_in[6];
    const float* Wcand_c = (const float*)d_in[7];
    const float* bcand_c = (const float*)d_in[8];
    const float* Wg      = (const float*)d_in[9];
    const float* bg      = (const float*)d_in[10];
    const float* lnug    = (const float*)d_in[11];
    const float* lnub    = (const float*)d_in[12];
    const float* lncg    = (const float*)d_in[13];
    const float* lncb    = (const float*)d_in[14];
    float* out = (float*)d_out;

    cudaFuncSetAttribute(k4a_mma, cudaFuncAttributeMaxDynamicSharedMemorySize, K4_SMEM);
    cudaFuncSetAttribute(k4b_mma, cudaFuncAttributeMaxDynamicSharedMemorySize, K4_SMEM);
    cudaFuncSetAttribute(k3_rec, cudaFuncAttributeMaxDynamicSharedMemorySize, K3W_SMEM);

    int prio_lo = 0, prio_hi = 0;
    cudaDeviceGetStreamPriorityRange(&prio_lo, &prio_hi);
    cudaStream_t s2;
    cudaStreamCreateWithPriority(&s2, cudaStreamNonBlocking, prio_hi);
    cudaEvent_t e1, e2;
    cudaEventCreateWithFlags(&e1, cudaEventDisableTiming);
    cudaEventCreateWithFlags(&e2, cudaEventDisableTiming);

    // main: prerequisites for both branches (serial, proven R11 ordering)
    k5_dinit<<<Cdim, 128>>>(base);
    k1_lnu<<<BT, 256>>>(u, lnug, lnub);
    k2_lu <<<BT, 256>>>(Wcu);
    cudaEventRecord(e1, 0);

    // high-priority branch: recurrence + c bf16 split (placed before k4a floods)
    cudaStreamWaitEvent(s2, e1, 0);
    k3_rec<<<Bdim, 256, K3W_SMEM, s2>>>(Wcc, valid, lncg, lncb);
    cudaEventRecord(e2, s2);

    // main: u-part GEMM (overlaps k3)
    k4a_mma<<<MC / 64, 256, K4_SMEM>>>(Wcand_u);

    // join, then c-part GEMM and the dictionary steps
    cudaStreamWaitEvent(0, e2, 0);
    k4b_mma<<<MC / 64, 256, K4_SMEM>>>(Wcand_c, bcand_u, bcand_c);
    k_steps<<<dim3(NTILE, Bdim), 256>>>(u, valid, Wg, bg, out);

    cudaEventDestroy(e1);
    cudaEventDestroy(e2);
    cudaStreamDestroy(s2);
}

// round 16
// speedup vs baseline: 1.2013x; 1.0248x over previous
#include <cuda_runtime.h>
#include <cuda_bf16.h>
#include <cstdint>

#define Mdim 512
#define Cdim 256
#define Bdim 8
#define Tdim 32
#define BT 256            // B*T
#define MC 131072         // M*C
#define TOPKK 8
#define LAMf 0.05f
#define RHOf 0.9f
#define DLRf 0.03f
#define EPSF 1e-12f
#define LN_EPSF 1e-5f
#define AP 776            // padded A row pitch (floats)
#define NTILE 32          // C / 8 column tiles
#define CPT 8             // columns per tile
#define CPITCH 520        // smem cand pitch

// ---------------- scratch (device globals; no allocation allowed) ----------
__device__ float g_LNu[BT * Mdim];
__device__ float g_A[BT * AP];                     // [u(512) | c_t(256)] rows
__device__ float g_Lu[BT * Cdim];
__device__ float g_ct[BT * Cdim];
__device__ int   g_aidx[BT * TOPKK];
__device__ float g_aval[BT * TOPKK];
__device__ float g_cand[(size_t)BT * MC];          // 128 MiB cand scratch / partials
__device__ float g_D[2][Bdim * Cdim * Mdim];       // ping-pong dictionary [b][c][m]
__device__ float g_zpart[(size_t)BT * NTILE * Mdim];
__device__ unsigned g_bar[Bdim];                   // per-batch step barriers (k_steps)
__device__ uint4 g_Abf_hi4[BT * 768 * 2 / 16];     // A hi bf16 (16B-aligned)
__device__ uint4 g_Abf_lo4[BT * 768 * 2 / 16];     // A lo bf16

// ---------------- helpers --------------------------------------------------
__device__ __forceinline__ uint32_t smem_u32(const void* p) {
    uint32_t a;
    asm("{ .reg .u64 t; cvta.to.shared.u64 t, %1; cvt.u32.u64 %0, t; }" : "=r"(a) : "l"(p));
    return a;
}
__device__ __forceinline__ void ldsm_x4(uint32_t* r, uint32_t addr) {
    asm volatile("ldmatrix.sync.aligned.m8n8.x4.shared.b16 {%0,%1,%2,%3}, [%4];"
        : "=r"(r[0]), "=r"(r[1]), "=r"(r[2]), "=r"(r[3]) : "r"(addr));
}
__device__ __forceinline__ void mma_bf16(float* c, const uint32_t* a, uint32_t b0, uint32_t b1) {
    asm volatile("mma.sync.aligned.m16n8k16.row.col.f32.bf16.bf16.f32 "
        "{%0,%1,%2,%3}, {%4,%5,%6,%7}, {%8,%9}, {%0,%1,%2,%3};"
        : "+f"(c[0]), "+f"(c[1]), "+f"(c[2]), "+f"(c[3])
        : "r"(a[0]), "r"(a[1]), "r"(a[2]), "r"(a[3]), "r"(b0), "r"(b1));
}
__device__ __forceinline__ void cpasync16(uint32_t dst, const void* src) {
    asm volatile("cp.async.cg.shared.global [%0], [%1], 16;" :: "r"(dst), "l"(src));
}
__device__ __forceinline__ float blockReduceSum(float v, float* sh) {
    __syncthreads();
    #pragma unroll
    for (int o = 16; o; o >>= 1) v += __shfl_xor_sync(0xffffffffu, v, o);
    int w = threadIdx.x >> 5, l = threadIdx.x & 31;
    if (l == 0) sh[w] = v;
    __syncthreads();
    if (w == 0) {
        float x = (l < (int)(blockDim.x >> 5)) ? sh[l] : 0.f;
        #pragma unroll
        for (int o = 4; o; o >>= 1) x += __shfl_xor_sync(0xffffffffu, x, o);
        if (l == 0) sh[0] = x;
    }
    __syncthreads();
    return sh[0];
}
__device__ __forceinline__ void bf_split(float v, __nv_bfloat16* ph, __nv_bfloat16* pl) {
    __nv_bfloat16 h = __float2bfloat16_rn(v);
    *ph = h;
    *pl = __float2bfloat16_rn(v - __bfloat162float(h));
}

// ---------------- K1: LN(u), fill A u-part + bf16 u split ------------------
__global__ void k1_lnu(const float* __restrict__ u,
                       const float* __restrict__ g, const float* __restrict__ bb) {
    __shared__ float sh[8];
    int r = blockIdx.x, tid = threadIdx.x;
    const float* ur = u + (size_t)r * Mdim;
    float x0 = ur[tid], x1 = ur[tid + 256];
    float s = blockReduceSum(x0 + x1, sh);
    float mu = s * (1.f / Mdim);
    float d0 = x0 - mu, d1 = x1 - mu;
    float var = blockReduceSum(d0 * d0 + d1 * d1, sh) * (1.f / Mdim);
    float inv = rsqrtf(var + LN_EPSF);
    g_LNu[(size_t)r * Mdim + tid]       = d0 * inv * g[tid] + bb[tid];
    g_LNu[(size_t)r * Mdim + tid + 256] = d1 * inv * g[tid + 256] + bb[tid + 256];
    g_A[(size_t)r * AP + tid]       = x0;
    g_A[(size_t)r * AP + tid + 256] = x1;
    __nv_bfloat16* ph = (__nv_bfloat16*)g_Abf_hi4;
    __nv_bfloat16* pl = (__nv_bfloat16*)g_Abf_lo4;
    bf_split(x0, ph + r * 768 + tid,       pl + r * 768 + tid);
    bf_split(x1, ph + r * 768 + tid + 256, pl + r * 768 + tid + 256);
}

// ---------------- K2: Lu = LN(u) @ W_cu^T ---------------------------------
__global__ void k2_lu(const float* __restrict__ Wcu) {
    __shared__ float ln[Mdim];
    int r = blockIdx.x, c = threadIdx.x;
    ln[c]       = g_LNu[(size_t)r * Mdim + c];
    ln[c + 256] = g_LNu[(size_t)r * Mdim + c + 256];
    __syncthreads();
    const float4* wr = (const float4*)(Wcu + (size_t)c * Mdim);
    float a0 = 0.f, a1 = 0.f, a2 = 0.f, a3 = 0.f;
    #pragma unroll 4
    for (int i = 0; i < 128; i += 4) {
        float4 w0 = wr[i],   w1 = wr[i+1], w2 = wr[i+2], w3 = wr[i+3];
        a0 = fmaf(w0.x, ln[4*i+0], fmaf(w0.y, ln[4*i+1], fmaf(w0.z, ln[4*i+2], fmaf(w0.w, ln[4*i+3], a0))));
        a1 = fmaf(w1.x, ln[4*i+4], fmaf(w1.y, ln[4*i+5], fmaf(w1.z, ln[4*i+6], fmaf(w1.w, ln[4*i+7], a1))));
        a2 = fmaf(w2.x, ln[4*i+8], fmaf(w2.y, ln[4*i+9], fmaf(w2.z, ln[4*i+10], fmaf(w2.w, ln[4*i+11], a2))));
        a3 = fmaf(w3.x, ln[4*i+12], fmaf(w3.y, ln[4*i+13], fmaf(w3.z, ln[4*i+14], fmaf(w3.w, ln[4*i+15], a3))));
    }
    g_Lu[r * Cdim + c] = (a0 + a1) + (a2 + a3);
}

// ---------------- K3: recurrence, Wcc resident (smem+regs) + c bf16 split --
#define K3_PITCH 130
#define K3W_SMEM (Cdim * K3_PITCH * 4)      // 133120 bytes

__global__ void __launch_bounds__(256, 1)
k3_rec(const float* __restrict__ Wcc, const float* __restrict__ valid,
       const float* __restrict__ lncg, const float* __restrict__ lncb) {
    extern __shared__ float wsm[];          // [256][K3_PITCH]
    __shared__ float sh[16];
    __shared__ float lnc[Cdim];
    __shared__ float shr_sm[Cdim];
    __shared__ float cwv[64];
    __shared__ int   cwi[64];
    __shared__ float t8v[TOPKK];
    __shared__ int   t8i[TOPKK];
    int b = blockIdx.x, c = threadIdx.x;
    int w = c >> 5, lane = c & 31;

    for (int idx = c; idx < Cdim * 128; idx += 256) {
        int r = idx >> 7, k = idx & 127;
        wsm[r * K3_PITCH + k] = Wcc[(size_t)r * Cdim + k];
    }
    float wreg[128];
    {
        const float4* wrow4 = (const float4*)(Wcc + (size_t)c * Cdim + 128);
        #pragma unroll
        for (int j = 0; j < 32; j++) {
            float4 v = wrow4[j];
            wreg[4*j+0] = v.x; wreg[4*j+1] = v.y;
            wreg[4*j+2] = v.z; wreg[4*j+3] = v.w;
        }
    }
    float cp = 0.f;
    float gC = lncg[c], bC = lncb[c];
    const float2* wr2 = (const float2*)(wsm + c * K3_PITCH);
    __nv_bfloat16* ph = (__nv_bfloat16*)g_Abf_hi4;
    __nv_bfloat16* pl = (__nv_bfloat16*)g_Abf_lo4;
    __syncthreads();

    for (int t = 0; t < Tdim; t++) {
        int bt = b * Tdim + t;
        float s1 = cp, s2 = cp * cp;
        #pragma unroll
        for (int o = 16; o; o >>= 1) {
            s1 += __shfl_xor_sync(0xffffffffu, s1, o);
            s2 += __shfl_xor_sync(0xffffffffu, s2, o);
        }
        if (lane == 0) { sh[w] = s1; sh[8 + w] = s2; }
        __syncthreads();
        float t1 = 0.f, t2 = 0.f;
        #pragma unroll
        for (int j = 0; j < 8; j++) { t1 += sh[j]; t2 += sh[8 + j]; }
        float mu  = t1 * (1.f / Cdim);
        float var = t2 * (1.f / Cdim) - mu * mu;
        float inv = rsqrtf(var + LN_EPSF);
        lnc[c] = (cp - mu) * inv * gC + bC;
        __syncthreads();
        const float2* l2 = (const float2*)lnc;
        float a0 = 0.f, a1 = 0.f, a2 = 0.f, a3 = 0.f;
        #pragma unroll
        for (int j = 0; j < 64; j += 4) {
            float2 w0 = wr2[j],   l0 = l2[j];
            float2 w1 = wr2[j+1], l1 = l2[j+1];
            float2 w2 = wr2[j+2], l2v = l2[j+2];
            float2 w3 = wr2[j+3], l3 = l2[j+3];
            a0 = fmaf(w0.x, l0.x,  fmaf(w0.y, l0.y,  a0));
            a1 = fmaf(w1.x, l1.x,  fmaf(w1.y, l1.y,  a1));
            a2 = fmaf(w2.x, l2v.x, fmaf(w2.y, l2v.y, a2));
            a3 = fmaf(w3.x, l3.x,  fmaf(w3.y, l3.y,  a3));
        }
        #pragma unroll
        for (int j = 0; j < 128; j += 4) {
            a0 = fmaf(wreg[j+0], lnc[128 + j + 0], a0);
            a1 = fmaf(wreg[j+1], lnc[128 + j + 1], a1);
            a2 = fmaf(wreg[j+2], lnc[128 + j + 2], a2);
            a3 = fmaf(wreg[j+3], lnc[128 + j + 3], a3);
        }
        float acc = g_Lu[bt * Cdim + c] + (a0 + a1) + (a2 + a3);
        float aa  = fabsf(acc) - LAMf;
        float shr = aa > 0.f ? copysignf(aa, acc) : 0.f;
        shr_sm[c] = shr;
        float myv = fabsf(shr); int myi = c;
        #pragma unroll
        for (int k = 0; k < TOPKK; k++) {
            float mv = myv; int mi = myi;
            #pragma unroll
            for (int o = 16; o; o >>= 1) {
                float ov = __shfl_xor_sync(0xffffffffu, mv, o);
                int   oi = __shfl_xor_sync(0xffffffffu, mi, o);
                if (ov > mv || (ov == mv && oi < mi)) { mv = ov; mi = oi; }
            }
            if (lane == 0) { cwv[w * 8 + k] = mv; cwi[w * 8 + k] = mi; }
            if (myi == mi) myv = -1.f;
        }
        __syncthreads();
        if (w == 0) {
            float v0 = cwv[lane], v1 = cwv[32 + lane];
            int   i0 = cwi[lane], i1 = cwi[32 + lane];
            #pragma unroll
            for (int k = 0; k < TOPKK; k++) {
                float bv; int bi;
                if (v0 > v1 || (v0 == v1 && i0 < i1)) { bv = v0; bi = i0; }
                else                                   { bv = v1; bi = i1; }
                #pragma unroll
                for (int o = 16; o; o >>= 1) {
                    float ov = __shfl_xor_sync(0xffffffffu, bv, o);
                    int   oi = __shfl_xor_sync(0xffffffffu, bi, o);
                    if (ov > bv || (ov == bv && oi < bi)) { bv = ov; bi = oi; }
                }
                if (lane == 0) {
                    float sv = shr_sm[bi];
                    t8v[k] = sv; t8i[k] = bi;
                    g_aidx[bt * TOPKK + k] = bi;
                    g_aval[bt * TOPKK + k] = sv;
                }
                if (i0 == bi) v0 = -1.f;
                if (i1 == bi) v1 = -1.f;
            }
        }
        __syncthreads();
        float ac = 0.f;
        #pragma unroll
        for (int j = 0; j < TOPKK; j++)
            if (t8i[j] == c) ac = t8v[j];
        float vv = valid[bt];
        float cn = RHOf * cp + (1.f - RHOf) * ac;
        cp = vv * cn + (1.f - vv) * cp;
        g_ct[bt * Cdim + c] = cp;
        g_A[(size_t)bt * AP + Mdim + c] = cp;
        bf_split(cp, ph + bt * 768 + 512 + c, pl + bt * 768 + 512 + c);
    }
}

// ---------------- K4: pipelined cand GEMM, split u-part / c-part -----------
#define SOFF_A 0            // 4 x 20480: hi0, lo0, hi1, lo1
#define SOFF_W_HI 81920
#define SOFF_W_LO 87040
#define SOFF_BIAS 92160
#define K4_SMEM   92416
#define APITCH 80   // bytes per smem A/W row (32 bf16 + 8 pad)

__device__ __forceinline__ void stage_A(uint32_t sb, int buf, int k0, int tid) {
    uint32_t hbase = sb + SOFF_A + buf * 40960;
    uint32_t lbase = hbase + 20480;
    #pragma unroll
    for (int i = 0; i < 4; i++) {
        int s = tid + i * 256;
        int row = s >> 2, qq = s & 3;
        size_t soff = ((size_t)row * 768 + k0) * 2 + qq * 16;
        cpasync16(hbase + row * APITCH + qq * 16, (const char*)g_Abf_hi4 + soff);
        cpasync16(lbase + row * APITCH + qq * 16, (const char*)g_Abf_lo4 + soff);
    }
}
__device__ __forceinline__ void ldW_s(const float* __restrict__ W, int sw,
                                      int n0, int k0, int tid, float4* w) {
    #pragma unroll
    for (int i = 0; i < 2; i++) {
        int s = tid + i * 256;
        int row = s >> 3, c4 = (s & 7) * 4;
        w[i] = *(const float4*)(W + (size_t)(n0 + row) * sw + k0 + c4);
    }
}
__device__ __forceinline__ void storeW_smem(char* sm, int tid, const float4* wreg) {
    #pragma unroll
    for (int i = 0; i < 2; i++) {
        int s = tid + i * 256;
        int row = s >> 3, c4 = (s & 7) * 4;
        float4 v = wreg[i];
        __nv_bfloat16 h0 = __float2bfloat16_rn(v.x), h1 = __float2bfloat16_rn(v.y);
        __nv_bfloat16 h2 = __float2bfloat16_rn(v.z), h3 = __float2bfloat16_rn(v.w);
        uint2 hi, lo;
        hi.x = (uint32_t)__bfloat16_as_ushort(h0) | ((uint32_t)__bfloat16_as_ushort(h1) << 16);
        hi.y = (uint32_t)__bfloat16_as_ushort(h2) | ((uint32_t)__bfloat16_as_ushort(h3) << 16);
        __nv_bfloat16 l0 = __float2bfloat16_rn(v.x - __bfloat162float(h0));
        __nv_bfloat16 l1 = __float2bfloat16_rn(v.y - __bfloat162float(h1));
        __nv_bfloat16 l2 = __float2bfloat16_rn(v.z - __bfloat162float(h2));
        __nv_bfloat16 l3 = __float2bfloat16_rn(v.w - __bfloat162float(h3));
        lo.x = (uint32_t)__bfloat16_as_ushort(l0) | ((uint32_t)__bfloat16_as_ushort(l1) << 16);
        lo.y = (uint32_t)__bfloat16_as_ushort(l2) | ((uint32_t)__bfloat16_as_ushort(l3) << 16);
        *(uint2*)(sm + SOFF_W_HI + row * APITCH + c4 * 2) = hi;
        *(uint2*)(sm + SOFF_W_LO + row * APITCH + c4 * 2) = lo;
    }
}
__device__ __forceinline__ void k4_compute(uint32_t sb, int buf,
                                           const uint32_t* aoff, const uint32_t* boff,
                                           float acc[4][4][4]) {
    uint32_t abh = sb + SOFF_A + buf * 40960;
    uint32_t abl = abh + 20480;
    #pragma unroll
    for (int kh = 0; kh < 2; kh++) {
        uint32_t ah[4][4], al[4][4];
        #pragma unroll
        for (int mt = 0; mt < 4; mt++) {
            ldsm_x4(ah[mt], abh + aoff[mt] + kh * 32);
            ldsm_x4(al[mt], abl + aoff[mt] + kh * 32);
        }
        #pragma unroll
        for (int np = 0; np < 2; np++) {
            uint32_t bh[4], bl[4];
            ldsm_x4(bh, sb + SOFF_W_HI + boff[np] + kh * 32);
            ldsm_x4(bl, sb + SOFF_W_LO + boff[np] + kh * 32);
            #pragma unroll
            for (int h = 0; h < 2; h++) {
                #pragma unroll
                for (int mt = 0; mt < 4; mt++)
                    mma_bf16(acc[mt][np * 2 + h], ah[mt], bh[h * 2], bh[h * 2 + 1]);
                #pragma unroll
                for (int mt = 0; mt < 4; mt++)
                    mma_bf16(acc[mt][np * 2 + h], ah[mt], bl[h * 2], bl[h * 2 + 1]);
                #pragma unroll
                for (int mt = 0; mt < 4; mt++)
                    mma_bf16(acc[mt][np * 2 + h], al[mt], bh[h * 2], bh[h * 2 + 1]);
            }
        }
    }
}
__device__ __forceinline__ void k4_offsets(int wm, int wn, int lane,
                                           uint32_t* aoff, uint32_t* boff) {
    #pragma unroll
    for (int mt = 0; mt < 4; mt++)
        aoff[mt] = (uint32_t)((wm * 64 + mt * 16 + (lane & 15)) * APITCH + (lane >> 4) * 16);
    #pragma unroll
    for (int np = 0; np < 2; np++)
        boff[np] = (uint32_t)((wn * 32 + np * 16 + (lane & 7) + ((lane >> 4) << 3)) * APITCH
                              + ((lane >> 3) & 1) * 16);
}

__global__ void __launch_bounds__(256, 2)
k4a_mma(const float* __restrict__ Wu) {
    extern __shared__ char sm[];
    uint32_t sb = smem_u32(sm);
    int tid = threadIdx.x, wid = tid >> 5, lane = tid & 31;
    int wm = wid & 3, wn = wid >> 2;
    int n0 = blockIdx.x * 64;

    float acc[4][4][4];
    #pragma unroll
    for (int i = 0; i < 4; i++)
        #pragma unroll
        for (int j = 0; j < 4; j++)
            #pragma unroll
            for (int k = 0; k < 4; k++) acc[i][j][k] = 0.f;
    uint32_t aoff[4], boff[2];
    k4_offsets(wm, wn, lane, aoff, boff);

    stage_A(sb, 0, 0, tid);
    asm volatile("cp.async.commit_group;" ::: "memory");
    float4 wreg[2];
    ldW_s(Wu, 512, n0, 0, tid, wreg);

    for (int q = 0; q < 16; q++) {
        int buf = q & 1;
        __syncthreads();
        storeW_smem(sm, tid, wreg);
        if (q + 1 < 16) {
            stage_A(sb, buf ^ 1, (q + 1) * 32, tid);
            asm volatile("cp.async.commit_group;" ::: "memory");
            ldW_s(Wu, 512, n0, (q + 1) * 32, tid, wreg);
            asm volatile("cp.async.wait_group 1;" ::: "memory");
        } else {
            asm volatile("cp.async.wait_group 0;" ::: "memory");
        }
        __syncthreads();
        k4_compute(sb, buf, aoff, boff, acc);
    }
    #pragma unroll
    for (int mt = 0; mt < 4; mt++) {
        int row = wm * 64 + mt * 16 + (lane >> 2);
        #pragma unroll
        for (int nf = 0; nf < 4; nf++) {
            int cl = wn * 32 + nf * 8 + (lane & 3) * 2;
            *(float2*)(g_cand + (size_t)row * MC + n0 + cl)       = make_float2(acc[mt][nf][0], acc[mt][nf][1]);
            *(float2*)(g_cand + (size_t)(row + 8) * MC + n0 + cl) = make_float2(acc[mt][nf][2], acc[mt][nf][3]);
        }
    }
}

__global__ void __launch_bounds__(256, 2)
k4b_mma(const float* __restrict__ Wc,
        const float* __restrict__ bu, const float* __restrict__ bc) {
    extern __shared__ char sm[];
    uint32_t sb = smem_u32(sm);
    int tid = threadIdx.x, wid = tid >> 5, lane = tid & 31;
    int wm = wid & 3, wn = wid >> 2;
    int n0 = blockIdx.x * 64;

    if (tid < 64) ((float*)(sm + SOFF_BIAS))[tid] = bu[n0 + tid] + bc[n0 + tid];

    uint32_t aoff[4], boff[2];
    k4_offsets(wm, wn, lane, aoff, boff);

    stage_A(sb, 0, 512, tid);
    asm volatile("cp.async.commit_group;" ::: "memory");
    float4 wreg[2];
    ldW_s(Wc, 256, n0, 0, tid, wreg);

    float acc[4][4][4];
    #pragma unroll
    for (int mt = 0; mt < 4; mt++) {
        int row = wm * 64 + mt * 16 + (lane >> 2);
        #pragma unroll
        for (int nf = 0; nf < 4; nf++) {
            int cl = wn * 32 + nf * 8 + (lane & 3) * 2;
            float2 p0 = *(const float2*)(g_cand + (size_t)row * MC + n0 + cl);
            float2 p1 = *(const float2*)(g_cand + (size_t)(row + 8) * MC + n0 + cl);
            acc[mt][nf][0] = p0.x; acc[mt][nf][1] = p0.y;
            acc[mt][nf][2] = p1.x; acc[mt][nf][3] = p1.y;
        }
    }

    for (int q = 0; q < 8; q++) {
        int buf = q & 1;
        __syncthreads();
        storeW_smem(sm, tid, wreg);
        if (q + 1 < 8) {
            stage_A(sb, buf ^ 1, 512 + (q + 1) * 32, tid);
            asm volatile("cp.async.commit_group;" ::: "memory");
            ldW_s(Wc, 256, n0, (q + 1) * 32, tid, wreg);
            asm volatile("cp.async.wait_group 1;" ::: "memory");
        } else {
            asm volatile("cp.async.wait_group 0;" ::: "memory");
        }
        __syncthreads();
        k4_compute(sb, buf, aoff, boff, acc);
    }
    const float* bias = (const float*)(sm + SOFF_BIAS);
    #pragma unroll
    for (int mt = 0; mt < 4; mt++) {
        int row = wm * 64 + mt * 16 + (lane >> 2);
        #pragma unroll
        for (int nf = 0; nf < 4; nf++) {
            int cl = wn * 32 + nf * 8 + (lane & 3) * 2;
            float b0 = bias[cl], b1 = bias[cl + 1];
            float2 v0 = make_float2(acc[mt][nf][0] + b0, acc[mt][nf][1] + b1);
            float2 v1 = make_float2(acc[mt][nf][2] + b0, acc[mt][nf][3] + b1);
            *(float2*)(g_cand + (size_t)row * MC + n0 + cl)       = v0;
            *(float2*)(g_cand + (size_t)(row + 8) * MC + n0 + cl) = v1;
        }
    }
}

// ---------------- K5: D0 init + barrier reset ------------------------------
__global__ void k5_dinit(const float* __restrict__ base) {
    __shared__ float sh[8];
    int c = blockIdx.x, tid = threadIdx.x;  // 128 threads
    if (c < Bdim && tid == 0) g_bar[c] = 0;
    float s = 0.f;
    for (int m = tid; m < Mdim; m += 128) {
        float v = base[(size_t)m * Cdim + c];
        s += v * v;
    }
    float stot = blockReduceSum(s, sh);
    float inv = 1.f / fmaxf(sqrtf(stot), EPSF);
    for (int b = 0; b < Bdim; b++)
        for (int m = tid; m < Mdim; m += 128)
            g_D[0][((size_t)b * Cdim + c) * Mdim + m] = base[(size_t)m * Cdim + c] * inv;
}

// ---------------- K6: persistent steps; D register-resident; cand prefetch -
__global__ void __launch_bounds__(256, 2)
k_steps(const float* __restrict__ u, const float* __restrict__ valid,
        const float* __restrict__ Wg, const float* __restrict__ bg,
        float* __restrict__ out) {
    __shared__ float sh[8];
    __shared__ float rsh[Mdim];
    __shared__ float ctsh[Cdim];
    __shared__ float cnd[2][CPT][CPITCH];
    __shared__ int   aidx[TOPKK];
    __shared__ float aval[TOPKK];
    __shared__ float gsh;
    int tile = blockIdx.x, b = blockIdx.y, tid = threadIdx.x;
    int c0 = tile * CPT;
    int w = tid >> 5, lane = tid & 31;
    int cc = c0 + w;

    // D columns resident in registers across steps
    float Dreg[16];
    {
        const float* Dc0 = g_D[0] + ((size_t)b * Cdim + cc) * Mdim;
        #pragma unroll
        for (int k = 0; k < 16; k++) Dreg[k] = Dc0[lane + 32 * k];
    }
    // prefetch cand(t=0)
    float4 cpre[4];
    {
        const float* cb = g_cand + (size_t)(b * Tdim) * MC + c0;
        #pragma unroll
        for (int it = 0; it < 4; it++) {
            int i = tid + it * 256;
            int m = i >> 1, half = i & 1;
            cpre[it] = *(const float4*)(cb + (size_t)m * Cdim + half * 4);
        }
    }

    for (int t = 0; t < Tdim; t++) {
        int pb = t & 1;
        const float* Dsrc = g_D[pb];
        float*       Ddst = g_D[pb ^ 1];
        int bt = b * Tdim + t;
        const float* ur = u + (size_t)bt * Mdim;
        float vv = valid[bt];
        ctsh[tid] = g_ct[bt * Cdim + tid];
        if (tid < TOPKK) { aidx[tid] = g_aidx[bt * TOPKK + tid]; aval[tid] = g_aval[bt * TOPKK + tid]; }
        // stage prefetched cand into smem buffer pb
        #pragma unroll
        for (int it = 0; it < 4; it++) {
            int i = tid + it * 256;
            int m = i >> 1, half = i & 1;
            int jb = half * 4;
            float4 v = cpre[it];
            cnd[pb][jb + 0][m] = v.x; cnd[pb][jb + 1][m] = v.y;
            cnd[pb][jb + 2][m] = v.z; cnd[pb][jb + 3][m] = v.w;
        }
        __syncthreads();
        float perr = 0.f, pg = 0.f;
        #pragma unroll
        for (int h = 0; h < 2; h++) {
            int m = tid + h * 256;
            float acc = ur[m];
            #pragma unroll
            for (int j = 0; j < TOPKK; j++)
                acc -= Dsrc[((size_t)b * Cdim + aidx[j]) * Mdim + m] * aval[j];
            rsh[m] = acc;
            perr += acc * acc;
            pg   += Wg[m] * ur[m];
        }
        pg += Wg[Mdim + tid] * ctsh[tid];
        float errsum = blockReduceSum(perr, sh);
        float gsum   = blockReduceSum(pg, sh);
        if (tid == 0) {
            float err = sqrtf(errsum);
            float gp  = gsum + Wg[Mdim + Cdim] * err + bg[0];
            gsh = 1.f / (1.f + expf(-gp));
        }
        __syncthreads();
        float g = gsh;
        float av = 0.f;
        #pragma unroll
        for (int j = 0; j < TOPKK; j++)
            if (aidx[j] == cc) av = aval[j];
        float* Do = Ddst + ((size_t)b * Cdim + cc) * Mdim;
        float sl = 0.f, sc2 = 0.f, sx = 0.f;
        float dla = DLRf * av;
        #pragma unroll
        for (int k = 0; k < 16; k++) {
            int m = lane + 32 * k;
            float dl = fmaf(dla, rsh[m], Dreg[k]);
            float cn = cnd[pb][w][m];
            sl  = fmaf(dl, dl, sl);
            sc2 = fmaf(cn, cn, sc2);
            sx  = fmaf(dl, cn, sx);
        }
        #pragma unroll
        for (int o = 16; o; o >>= 1) {
            sl  += __shfl_xor_sync(0xffffffffu, sl,  o);
            sc2 += __shfl_xor_sync(0xffffffffu, sc2, o);
            sx  += __shfl_xor_sync(0xffffffffu, sx,  o);
        }
        float il  = 1.f / fmaxf(sqrtf(sl),  EPSF);
        float icn = 1.f / fmaxf(sqrtf(sc2), EPSF);
        float w1 = (1.f - g) * il, w2 = g * icn;
        float smix = w1 * w1 * sl + 2.f * w1 * w2 * sx + w2 * w2 * sc2;
        float imix = 1.f / fmaxf(sqrtf(smix), EPSF);
        float ctc = ctsh[cc];
        #pragma unroll
        for (int k = 0; k < 16; k++) {
            int m = lane + 32 * k;
            float dl  = fmaf(dla, rsh[m], Dreg[k]);
            float cn  = cnd[pb][w][m];
            float mix = w1 * dl + w2 * cn;
            float dn  = vv * (mix * imix) + (1.f - vv) * Dreg[k];
            Dreg[k] = dn;
            Do[m] = dn;
            cnd[pb][w][m] = dn * ctc;
        }
        __syncthreads();
        float* zp = g_zpart + ((size_t)bt * NTILE + tile) * Mdim;
        for (int m = tid; m < Mdim; m += 256) {
            float z = 0.f;
            #pragma unroll
            for (int j = 0; j < CPT; j++) z += cnd[pb][j][m];
            zp[m] = z;
        }
        // prefetch cand(t+1) — latency hides under the barrier below
        if (t + 1 < Tdim) {
            const float* cb = g_cand + (size_t)(bt + 1) * MC + c0;
            #pragma unroll
            for (int it = 0; it < 4; it++) {
                int i = tid + it * 256;
                int m = i >> 1, half = i & 1;
                cpre[it] = *(const float4*)(cb + (size_t)m * Cdim + half * 4);
            }
        }
        __threadfence();
        __syncthreads();
        if (tid == 0) atomicAdd(&g_bar[b], 1u);
        if (t + 1 < Tdim) {
            if (tid == 0) {
                unsigned tgt = (unsigned)((t + 1) * NTILE);
                while (atomicAdd(&g_bar[b], 0u) < tgt) __nanosleep(32);
            }
            __syncthreads();
            __threadfence();
        }
    }
    if (tid == 0) {
        while (atomicAdd(&g_bar[b], 0u) < (unsigned)(Tdim * NTILE)) __nanosleep(32);
    }
    __syncthreads();
    __threadfence();
    int obt = b * Tdim + tile;       // NTILE == Tdim == 32
    const float* zp = g_zpart + (size_t)obt * NTILE * Mdim;
    for (int m = tid; m < Mdim; m += 256) {
        float s = 0.f;
        #pragma unroll
        for (int j = 0; j < NTILE; j++) s += zp[(size_t)j * Mdim + m];
        out[obt * Mdim + m] = s;
    }
}

// ---------------- launch: R15 structure (proven) ---------------------------
extern "C" void kernel_launch(void* const* d_in, const int* in_sizes, int n_in,
                              void* d_out, int out_size) {
    const float* u       = (const float*)d_in[0];
    const float* valid   = (const float*)d_in[1];
    const float* base    = (const float*)d_in[2];
    const float* Wcu     = (const float*)d_in[3];
    const float* Wcc     = (const float*)d_in[4];
    const float* Wcand_u = (const float*)d_in[5];
    const float* bcand_u = (const float*)d_in[6];
    const float* Wcand_c = (const float*)d_in[7];
    const float* bcand_c = (const float*)d_in[8];
    const float* Wg      = (const float*)d_in[9];
    const float* bg      = (const float*)d_in[10];
    const float* lnug    = (const float*)d_in[11];
    const float* lnub    = (const float*)d_in[12];
    const float* lncg    = (const float*)d_in[13];
    const float* lncb    = (const float*)d_in[14];
    float* out = (float*)d_out;

    cudaFuncSetAttribute(k4a_mma, cudaFuncAttributeMaxDynamicSharedMemorySize, K4_SMEM);
    cudaFuncSetAttribute(k4b_mma, cudaFuncAttributeMaxDynamicSharedMemorySize, K4_SMEM);
    cudaFuncSetAttribute(k3_rec, cudaFuncAttributeMaxDynamicSharedMemorySize, K3W_SMEM);

    int prio_lo = 0, prio_hi = 0;
    cudaDeviceGetStreamPriorityRange(&prio_lo, &prio_hi);
    cudaStream_t s2;
    cudaStreamCreateWithPriority(&s2, cudaStreamNonBlocking, prio_hi);
    cudaEvent_t e1, e2;
    cudaEventCreateWithFlags(&e1, cudaEventDisableTiming);
    cudaEventCreateWithFlags(&e2, cudaEventDisableTiming);

    // main: prerequisites for both branches (serial, proven ordering)
    k5_dinit<<<Cdim, 128>>>(base);
    k1_lnu<<<BT, 256>>>(u, lnug, lnub);
    k2_lu <<<BT, 256>>>(Wcu);
    cudaEventRecord(e1, 0);

    // high-priority branch: recurrence + c bf16 split (placed before k4a floods)
    cudaStreamWaitEvent(s2, e1, 0);
    k3_rec<<<Bdim, 256, K3W_SMEM, s2>>>(Wcc, valid, lncg, lncb);
    cudaEventRecord(e2, s2);

    // main: u-part GEMM (overlaps k3)
    k4a_mma<<<MC / 64, 256, K4_SMEM>>>(Wcand_u);

    // join, then c-part GEMM and the dictionary steps
    cudaStreamWaitEvent(0, e2, 0);
    k4b_mma<<<MC / 64, 256, K4_SMEM>>>(Wcand_c, bcand_u, bcand_c);
    k_steps<<<dim3(NTILE, Bdim), 256>>>(u, valid, Wg, bg, out);

    cudaEventDestroy(e1);
    cudaEventDestroy(e2);
    cudaStreamDestroy(s2);
}